// round 12
// baseline (speedup 1.0000x reference)
#include <cuda_runtime.h>
#include <cuda_bf16.h>
#include <cstdint>

// Problem constants (fixed shapes from the reference)
#define NB_B 8
#define NB_L 160
#define NB_H 512
#define NB_C 8
#define NB_S 64
#define NB_R 8
#define NB_BL (NB_B*NB_L)   // 1280
#define SC_PLANE (NB_B*NB_L*NB_L)   // 204800
#define XPLANE (NB_BL*NB_H)         // 655360
#define WPL (NB_H*NB_H)             // 262144
#define WMPLANE (NB_C*NB_H*NB_S)    // 262144

// ---------------- scratch (device globals: no runtime allocation) -------------
__device__ float g_vv [XPLANE];
__device__ __nv_bfloat16 g_vs [2*XPLANE];
__device__ __nv_bfloat16 g_ks [2*XPLANE];
__device__ __nv_bfloat16 g_qs [2*XPLANE];
__device__ __nv_bfloat16 g_wvs[2*WPL];
__device__ __nv_bfloat16 g_wml[2*WPL];      // w_m split
__device__ __nv_bfloat16 g_w0k[2*WPL];      // composed, bf16 planes
__device__ __nv_bfloat16 g_w1q[2*WPL];
__device__ float g_bc [2*NB_H];
__device__ __nv_bfloat16 g_x0 [2*XPLANE];
__device__ __nv_bfloat16 g_x1 [2*XPLANE];
__device__ __nv_bfloat16 g_wms[2][2*WMPLANE];
// Y layout: [b][c][s(64)][r(16: 8 hi | 8 lo)][l(160)] bf16
__device__ __nv_bfloat16 g_y0 [NB_B*NB_C*NB_S*16*NB_L];
__device__ __nv_bfloat16 g_y1 [NB_B*NB_C*NB_S*16*NB_L];
__device__ float g_sc [8*SC_PLANE];
__device__ __nv_bfloat16 g_scr[2*XPLANE];   // atted, bf16 planes

// ======================= mma.sync helpers (sm_80+ path) =======================
__device__ __forceinline__ uint32_t smem_u32(const void* p) {
    uint32_t a;
    asm("{ .reg .u64 t; cvta.to.shared.u64 t, %1; cvt.u32.u64 %0, t; }"
        : "=r"(a) : "l"(p));
    return a;
}
__device__ __forceinline__ void mma16816(float* d, const uint32_t* a, const uint32_t* b) {
    asm volatile(
        "mma.sync.aligned.m16n8k16.row.col.f32.bf16.bf16.f32 "
        "{%0,%1,%2,%3}, {%4,%5,%6,%7}, {%8,%9}, {%0,%1,%2,%3};"
        : "+f"(d[0]), "+f"(d[1]), "+f"(d[2]), "+f"(d[3])
        : "r"(a[0]), "r"(a[1]), "r"(a[2]), "r"(a[3]), "r"(b[0]), "r"(b[1]));
}
__device__ __forceinline__ void ldsm_x4(uint32_t* r, uint32_t addr) {
    asm volatile("ldmatrix.sync.aligned.m8n8.x4.shared.b16 {%0,%1,%2,%3}, [%4];"
        : "=r"(r[0]), "=r"(r[1]), "=r"(r[2]), "=r"(r[3]) : "r"(addr));
}
__device__ __forceinline__ void ldsm_x4t(uint32_t* r, uint32_t addr) {
    asm volatile("ldmatrix.sync.aligned.m8n8.x4.trans.shared.b16 {%0,%1,%2,%3}, [%4];"
        : "=r"(r[0]), "=r"(r[1]), "=r"(r[2]), "=r"(r[3]) : "r"(addr));
}
__device__ __forceinline__ void mma1688_z(float* d, uint32_t a0, uint32_t a1, uint32_t b) {
    asm volatile(
        "mma.sync.aligned.m16n8k8.row.col.f32.bf16.bf16.f32 "
        "{%0,%1,%2,%3}, {%4,%5}, {%6}, {%7,%8,%9,%10};"
        : "=f"(d[0]), "=f"(d[1]), "=f"(d[2]), "=f"(d[3])
        : "r"(a0), "r"(a1), "r"(b), "f"(0.f), "f"(0.f), "f"(0.f), "f"(0.f));
}
__device__ __forceinline__ void mma1688_acc(float* d, uint32_t a0, uint32_t a1, uint32_t b) {
    asm volatile(
        "mma.sync.aligned.m16n8k8.row.col.f32.bf16.bf16.f32 "
        "{%0,%1,%2,%3}, {%4,%5}, {%6}, {%0,%1,%2,%3};"
        : "+f"(d[0]), "+f"(d[1]), "+f"(d[2]), "+f"(d[3])
        : "r"(a0), "r"(a1), "r"(b));
}
__device__ __forceinline__ void cp16(uint32_t dst, const void* src) {
    asm volatile("cp.async.cg.shared.global [%0], [%1], 16;" :: "r"(dst), "l"(src));
}
__device__ __forceinline__ void cp8(uint32_t dst, const void* src) {
    asm volatile("cp.async.ca.shared.global [%0], [%1], 8;" :: "r"(dst), "l"(src));
}
__device__ __forceinline__ void split_store(__nv_bfloat16* smh, __nv_bfloat16* sml,
                                            int off, float4 v) {
    __nv_bfloat162 h01 = __floats2bfloat162_rn(v.x, v.y);
    __nv_bfloat162 h23 = __floats2bfloat162_rn(v.z, v.w);
    float2 f01 = __bfloat1622float2(h01);
    float2 f23 = __bfloat1622float2(h23);
    __nv_bfloat162 l01 = __floats2bfloat162_rn(v.x - f01.x, v.y - f01.y);
    __nv_bfloat162 l23 = __floats2bfloat162_rn(v.z - f23.x, v.w - f23.y);
    *(uint2*)&smh[off] = make_uint2(*(uint32_t*)&h01, *(uint32_t*)&h23);
    *(uint2*)&sml[off] = make_uint2(*(uint32_t*)&l01, *(uint32_t*)&l23);
}
__device__ __forceinline__ uint32_t pack_hilo(float v) {
    __nv_bfloat16 hi = __float2bfloat16(v);
    __nv_bfloat16 lo = __float2bfloat16(v - __bfloat162float(hi));
    return (uint32_t)*(uint16_t*)&hi | ((uint32_t)*(uint16_t*)&lo << 16);
}
__device__ __forceinline__ void split_pair(float a, float b, uint32_t& h, uint32_t& l) {
    __nv_bfloat162 hp = __floats2bfloat162_rn(a, b);
    float2 f = __bfloat1622float2(hp);
    __nv_bfloat162 lp = __floats2bfloat162_rn(a - f.x, b - f.y);
    h = *(uint32_t*)&hp;
    l = *(uint32_t*)&lp;
}

// =============== pure-bf16 tensor-core GEMM: C = A @ W^T + bias ==============
// A: bf16 hi plane (lo at +Astride), row-major [M,512]. W likewise [N,512].
// pack != 0 -> C written as bf16 hi/lo planes (stride XPLANE); else fp32.
struct GemmB {
    const __nv_bfloat16* A[3]; int Astride[3];
    const __nv_bfloat16* W[3]; int Wstride[3];
    const float* bias[3]; float* C[3]; int pack[3];
};

#define GS 40
#define G_AH 0
#define G_AL 5120
#define G_WH 10240
#define G_WL 12800
#define G_BUF 15360                  // halves per buffer
#define G_SMEM (2*G_BUF*2)           // 61440 bytes

__global__ void __launch_bounds__(256) bf16_gemm_kernel(GemmB gb)
{
    extern __shared__ __nv_bfloat16 sm[];
    const int tid = threadIdx.x;
    const int wid = tid >> 5, lane = tid & 31;
    const int z = blockIdx.z;
    const __nv_bfloat16* A = gb.A[z]; const int As = gb.Astride[z];
    const __nv_bfloat16* W = gb.W[z]; const int Ws = gb.Wstride[z];
    const float* bias = gb.bias[z];
    float* C = gb.C[z];
    const int m0 = blockIdx.x * 128;
    const int n0 = blockIdx.y * 64;
    const int wm = wid & 3, wn = wid >> 2;
    const uint32_t sb = smem_u32(sm);

    const int a_row = wm * 32 + (lane & 15);
    const uint32_t a_addr0 = sb + (uint32_t)((G_AH + a_row * GS + (lane >> 4) * 8) * 2);
    const int b_row = wn * 32 + ((lane >> 4) & 1) * 8 + (lane & 7);
    const uint32_t b_addr0 = sb + (uint32_t)((G_WH + b_row * GS + ((lane >> 3) & 1) * 8) * 2);

    auto issue = [&](int kc, int buf) {
        const int kbase = kc * 32;
        const uint32_t bo = (uint32_t)(buf * G_BUF * 2);
        #pragma unroll
        for (int it = 0; it < 4; it++) {          // A: 1024 16B units
            int u = tid + it * 256;
            int plane = u >> 9, vv2 = u & 511;
            int row = vv2 >> 2, g = vv2 & 3;
            const __nv_bfloat16* src = A + (size_t)plane * As
                + (size_t)(m0 + row) * 512 + kbase + g * 8;
            uint32_t dst = sb + bo + (uint32_t)(((plane ? G_AL : G_AH) + row * GS + g * 8) * 2);
            cp16(dst, src);
        }
        #pragma unroll
        for (int it = 0; it < 2; it++) {          // W: 512 16B units
            int u = tid + it * 256;
            int plane = u >> 8, vv2 = u & 255;
            int row = vv2 >> 2, g = vv2 & 3;
            const __nv_bfloat16* src = W + (size_t)plane * Ws
                + (size_t)(n0 + row) * 512 + kbase + g * 8;
            uint32_t dst = sb + bo + (uint32_t)(((plane ? G_WL : G_WH) + row * GS + g * 8) * 2);
            cp16(dst, src);
        }
        asm volatile("cp.async.commit_group;" ::: "memory");
    };

    float acc[2][4][4] = {};
    issue(0, 0);
    for (int kc = 0; kc < 16; kc++) {
        const int buf = kc & 1;
        if (kc < 15) {
            issue(kc + 1, buf ^ 1);
            asm volatile("cp.async.wait_group 1;" ::: "memory");
        } else {
            asm volatile("cp.async.wait_group 0;" ::: "memory");
        }
        __syncthreads();
        const uint32_t bo = (uint32_t)(buf * G_BUF * 2);
        #pragma unroll
        for (int k16 = 0; k16 < 2; k16++) {
            const uint32_t kb = (uint32_t)(k16 * 32);
            uint32_t ah[2][4], al[2][4];
            ldsm_x4(ah[0], a_addr0 + bo + kb);
            ldsm_x4(ah[1], a_addr0 + bo + (uint32_t)(16 * GS * 2) + kb);
            ldsm_x4(al[0], a_addr0 + bo + (uint32_t)(G_AL * 2) + kb);
            ldsm_x4(al[1], a_addr0 + bo + (uint32_t)(G_AL * 2 + 16 * GS * 2) + kb);
            uint32_t bh[2][4], bl[2][4];
            ldsm_x4(bh[0], b_addr0 + bo + kb);
            ldsm_x4(bh[1], b_addr0 + bo + (uint32_t)(16 * GS * 2) + kb);
            ldsm_x4(bl[0], b_addr0 + bo + (uint32_t)((G_WL - G_WH) * 2) + kb);
            ldsm_x4(bl[1], b_addr0 + bo + (uint32_t)((G_WL - G_WH) * 2 + 16 * GS * 2) + kb);
            #pragma unroll
            for (int mi = 0; mi < 2; mi++) {
                #pragma unroll
                for (int nj = 0; nj < 4; nj++) {
                    const uint32_t* bph = &bh[nj >> 1][(nj & 1) * 2];
                    const uint32_t* bpl = &bl[nj >> 1][(nj & 1) * 2];
                    mma16816(acc[mi][nj], ah[mi], bph);
                    mma16816(acc[mi][nj], ah[mi], bpl);
                    mma16816(acc[mi][nj], al[mi], bph);
                }
            }
        }
        __syncthreads();
    }

    const int mrow = m0 + wm * 32 + (lane >> 2);
    const int ncol = n0 + wn * 32 + (lane & 3) * 2;
    if (gb.pack[z]) {
        __nv_bfloat16* Ch = (__nv_bfloat16*)C;
        __nv_bfloat16* Cl = Ch + XPLANE;
        #pragma unroll
        for (int mi = 0; mi < 2; mi++) {
            #pragma unroll
            for (int nj = 0; nj < 4; nj++) {
                int n = ncol + nj * 8;
                float b0 = bias[n], b1 = bias[n + 1];
                int m_a = mrow + mi * 16;
                uint32_t h, l;
                split_pair(acc[mi][nj][0] + b0, acc[mi][nj][1] + b1, h, l);
                *(uint32_t*)&Ch[m_a * 512 + n] = h;
                *(uint32_t*)&Cl[m_a * 512 + n] = l;
                split_pair(acc[mi][nj][2] + b0, acc[mi][nj][3] + b1, h, l);
                *(uint32_t*)&Ch[(m_a + 8) * 512 + n] = h;
                *(uint32_t*)&Cl[(m_a + 8) * 512 + n] = l;
            }
        }
    } else {
        #pragma unroll
        for (int mi = 0; mi < 2; mi++) {
            #pragma unroll
            for (int nj = 0; nj < 4; nj++) {
                int n = ncol + nj * 8;
                float b0 = bias[n], b1 = bias[n + 1];
                int m_a = mrow + mi * 16;
                *(float2*)&C[m_a * 512 + n]       = make_float2(acc[mi][nj][0] + b0, acc[mi][nj][1] + b1);
                *(float2*)&C[(m_a + 8) * 512 + n] = make_float2(acc[mi][nj][2] + b0, acc[mi][nj][3] + b1);
            }
        }
    }
}

// ------------------------------------------------------------------------------
// Weight composition (NN GEMM, fp32 inputs): emits bf16 hi/lo planes.
#define LDA_S 72
#define OFF_AH 0
#define OFF_AL (128*LDA_S)
#define OFF_WH (256*LDA_S)
#define OFF_WL (320*LDA_S)
#define HM_SMEM_BYTES (384*LDA_S*2)   // 55296

__global__ void __launch_bounds__(256) prep_hmma_kernel(
    const float* __restrict__ A0, const float* __restrict__ B0, __nv_bfloat16* __restrict__ C0,
    const float* __restrict__ A1, const float* __restrict__ B1, __nv_bfloat16* __restrict__ C1)
{
    extern __shared__ __nv_bfloat16 sm[];
    const int tid  = threadIdx.x;
    const int wid  = tid >> 5, lane = tid & 31;
    const float* A = blockIdx.z ? A1 : A0;
    const float* B = blockIdx.z ? B1 : B0;
    __nv_bfloat16* C = blockIdx.z ? C1 : C0;
    const int m0 = blockIdx.x * 128;
    const int n0 = blockIdx.y * 64;
    const int wm = wid & 3, wn = wid >> 2;
    const uint32_t sb = smem_u32(sm);

    float acc[2][4][4] = {};

    const int a_row = wm * 32 + (lane & 15);
    const uint32_t a_addr0 = sb + (uint32_t)((OFF_AH + a_row * LDA_S + (lane >> 4) * 8) * 2);
    const int tb_row = ((lane >> 3) & 1) * 8 + (lane & 7);
    const int tb_col = wn * 32 + (lane >> 4) * 8;
    const uint32_t ALO_B = (uint32_t)((OFF_AL - OFF_AH) * 2);
    const uint32_t WLO_B = (uint32_t)((OFF_WL - OFF_WH) * 2);

    const int arow = tid >> 4, akg = (tid & 15) << 2;
    float4 pa[8], pw[4];
    #pragma unroll
    for (int it = 0; it < 8; it++)
        pa[it] = *(const float4*)(A + (m0 + arow + it * 16) * 512 + akg);
    #pragma unroll
    for (int it = 0; it < 4; it++)
        pw[it] = *(const float4*)(B + (arow + it * 16) * 512 + n0 + akg);

    for (int kc = 0; kc < 8; kc++) {
        __syncthreads();
        #pragma unroll
        for (int it = 0; it < 8; it++)
            split_store(sm + OFF_AH, sm + OFF_AL, (arow + it * 16) * LDA_S + akg, pa[it]);
        #pragma unroll
        for (int it = 0; it < 4; it++)
            split_store(sm + OFF_WH, sm + OFF_WL, (arow + it * 16) * LDA_S + akg, pw[it]);
        __syncthreads();

        if (kc < 7) {
            const int kb2 = (kc + 1) * 64;
            #pragma unroll
            for (int it = 0; it < 8; it++)
                pa[it] = *(const float4*)(A + (m0 + arow + it * 16) * 512 + kb2 + akg);
            #pragma unroll
            for (int it = 0; it < 4; it++)
                pw[it] = *(const float4*)(B + (kb2 + arow + it * 16) * 512 + n0 + akg);
        }

        #pragma unroll
        for (int k16 = 0; k16 < 4; k16++) {
            const uint32_t kb = (uint32_t)(k16 * 32);
            uint32_t ah[2][4], al[2][4];
            ldsm_x4(ah[0], a_addr0 + kb);
            ldsm_x4(ah[1], a_addr0 + (uint32_t)(16 * LDA_S * 2) + kb);
            ldsm_x4(al[0], a_addr0 + ALO_B + kb);
            ldsm_x4(al[1], a_addr0 + ALO_B + (uint32_t)(16 * LDA_S * 2) + kb);
            uint32_t bh[2][4], bl[2][4];
            const uint32_t bo = sb + (uint32_t)((OFF_WH + (k16 * 16 + tb_row) * LDA_S + tb_col) * 2);
            ldsm_x4t(bh[0], bo);
            ldsm_x4t(bh[1], bo + 32);
            ldsm_x4t(bl[0], bo + WLO_B);
            ldsm_x4t(bl[1], bo + WLO_B + 32);
            #pragma unroll
            for (int mi = 0; mi < 2; mi++) {
                #pragma unroll
                for (int nj = 0; nj < 4; nj++) {
                    const uint32_t* bph = &bh[nj >> 1][(nj & 1) * 2];
                    const uint32_t* bpl = &bl[nj >> 1][(nj & 1) * 2];
                    mma16816(acc[mi][nj], ah[mi], bph);
                    mma16816(acc[mi][nj], ah[mi], bpl);
                    mma16816(acc[mi][nj], al[mi], bph);
                }
            }
        }
    }

    const int mrow = m0 + wm * 32 + (lane >> 2);
    const int ncol = n0 + wn * 32 + (lane & 3) * 2;
    __nv_bfloat16* Cl = C + WPL;
    #pragma unroll
    for (int mi = 0; mi < 2; mi++) {
        #pragma unroll
        for (int nj = 0; nj < 4; nj++) {
            int n = ncol + nj * 8;
            int m_a = mrow + mi * 16;
            uint32_t h, l;
            split_pair(acc[mi][nj][0], acc[mi][nj][1], h, l);
            *(uint32_t*)&C[m_a * 512 + n]  = h;
            *(uint32_t*)&Cl[m_a * 512 + n] = l;
            split_pair(acc[mi][nj][2], acc[mi][nj][3], h, l);
            *(uint32_t*)&C[(m_a + 8) * 512 + n]  = h;
            *(uint32_t*)&Cl[(m_a + 8) * 512 + n] = l;
        }
    }
}

// ------------------------------------------------------------------------------
__global__ void __launch_bounds__(256) bias_comp_kernel(
    const float* __restrict__ w0, const float* __restrict__ bk, const float* __restrict__ b0,
    const float* __restrict__ w1, const float* __restrict__ bq, const float* __restrict__ b1,
    float* __restrict__ bc)
{
    const int z = blockIdx.y;
    const float* W  = z ? w1 : w0;
    const float* bi = z ? bq : bk;
    const float* bo = z ? b1 : b0;
    const int warp = threadIdx.x >> 5, lane = threadIdx.x & 31;
    const int n = blockIdx.x * 8 + warp;
    const float* row = W + n * 512;
    float s = 0.f;
    #pragma unroll 4
    for (int h = lane; h < 512; h += 32) s = fmaf(row[h], bi[h], s);
    #pragma unroll
    for (int o = 16; o; o >>= 1) s += __shfl_xor_sync(0xffffffffu, s, o);
    if (lane == 0) bc[z * 512 + n] = s + bo[n];
}

// ------------------------------------------------------------------------------
// Generic fp32 -> bf16 hi/lo plane split for 5 tensors.
// grid (640, 5): z=0..2 -> v/k/q (XPLANE), z=3..4 -> w_v/w_m (WPL).
__global__ void __launch_bounds__(256) split5_kernel(
    const float* __restrict__ v, const float* __restrict__ k, const float* __restrict__ q,
    const float* __restrict__ wv, const float* __restrict__ wm,
    __nv_bfloat16* __restrict__ vs, __nv_bfloat16* __restrict__ ks,
    __nv_bfloat16* __restrict__ qs, __nv_bfloat16* __restrict__ wvs,
    __nv_bfloat16* __restrict__ wml)
{
    const int z = blockIdx.y;
    const float* src; __nv_bfloat16* dst; int n;
    switch (z) {
        case 0: src = v;  dst = vs;  n = XPLANE; break;
        case 1: src = k;  dst = ks;  n = XPLANE; break;
        case 2: src = q;  dst = qs;  n = XPLANE; break;
        case 3: src = wv; dst = wvs; n = WPL;    break;
        default: src = wm; dst = wml; n = WPL;   break;
    }
    int i = blockIdx.x * 1024 + threadIdx.x * 4;
    if (i >= n) return;
    float4 val = *(const float4*)(src + i);
    uint32_t h01, l01, h23, l23;
    split_pair(val.x, val.y, h01, l01);
    split_pair(val.z, val.w, h23, l23);
    *(uint2*)&dst[i]     = make_uint2(h01, h23);
    *(uint2*)&dst[n + i] = make_uint2(l01, l23);
}

// ------------------------------------------------------------------------------
// wm split: fp32 merge weights -> bf16 hi/lo planes.
__global__ void __launch_bounds__(256) wm_split_kernel(
    const float* __restrict__ wm0, const float* __restrict__ wm1,
    __nv_bfloat16* __restrict__ wms)
{
    const int t = blockIdx.y;
    const float* src = t ? wm1 : wm0;
    __nv_bfloat16* dh = wms + (size_t)t * 2 * WMPLANE;
    __nv_bfloat16* dl = dh + WMPLANE;
    const int base4 = blockIdx.x * 512 + threadIdx.x * 2;
    #pragma unroll
    for (int j = 0; j < 2; j++) {
        int i4 = base4 + j;
        float4 v = *(const float4*)(src + i4 * 4);
        uint32_t h01, l01, h23, l23;
        split_pair(v.x, v.y, h01, l01);
        split_pair(v.z, v.w, h23, l23);
        *(uint2*)&dh[i4 * 4] = make_uint2(h01, h23);
        *(uint2*)&dl[i4 * 4] = make_uint2(l01, l23);
    }
}

// ------------------------------------------------------------------------------
// Tensor-core merge (unchanged from R11: cp.async pre-split planes).
struct MergeBatch {
    const __nv_bfloat16* X[2];
    const __nv_bfloat16* WMS[2];
    const float* BM[2];
    __nv_bfloat16* Y[2];
};

__global__ void __launch_bounds__(256) merge_tc_kernel(MergeBatch mb)
{
    extern __shared__ __nv_bfloat16 sm[];
    const int tid  = threadIdx.x;
    const int wid  = tid >> 5, lane = tid & 31;
    const int zz = blockIdx.z;
    const int tensor = zz >> 3, c = zz & 7;
    const __nv_bfloat16* X   = mb.X[tensor];
    const __nv_bfloat16* WMS = mb.WMS[tensor];
    const float* BM = mb.BM[tensor];
    __nv_bfloat16* Y = mb.Y[tensor];
    const int m0 = blockIdx.x * 128;
    const int r  = blockIdx.y;
    const int n0 = r * 64;
    const int wm = wid & 3, wn = wid >> 2;
    const uint32_t sb = smem_u32(sm);

    #pragma unroll
    for (int it = 0; it < 16; it++) {
        int u = tid + it * 256;
        int plane = u >> 11, v = u & 2047;
        int row = v >> 4, g = v & 15;
        const __nv_bfloat16* src = X + plane * XPLANE
            + (size_t)(m0 + row) * 512 + c * 64 + g * 4;
        uint32_t dst = sb + (uint32_t)(((plane ? OFF_AL : OFF_AH) + row * LDA_S + g * 4) * 2);
        cp8(dst, src);
    }
    #pragma unroll
    for (int it = 0; it < 8; it++) {
        int u = tid + it * 256;
        int plane = u >> 10, v = u & 1023;
        int row = v >> 4, g = v & 15;
        const __nv_bfloat16* src = WMS + plane * WMPLANE
            + (size_t)(c * 512 + n0 + row) * 64 + g * 4;
        uint32_t dst = sb + (uint32_t)(((plane ? OFF_WL : OFF_WH) + row * LDA_S + g * 4) * 2);
        cp8(dst, src);
    }
    asm volatile("cp.async.commit_group;" ::: "memory");
    asm volatile("cp.async.wait_group 0;" ::: "memory");
    __syncthreads();

    const int a_row = wm * 32 + (lane & 15);
    const uint32_t a_addr0 = sb + (uint32_t)((OFF_AH + a_row * LDA_S + (lane >> 4) * 8) * 2);
    const int b_row = wn * 32 + ((lane >> 4) & 1) * 8 + (lane & 7);
    const uint32_t b_addr0 = sb + (uint32_t)((OFF_WH + b_row * LDA_S + ((lane >> 3) & 1) * 8) * 2);
    const uint32_t ALO_B = (uint32_t)((OFF_AL - OFF_AH) * 2);
    const uint32_t WLO_B = (uint32_t)((OFF_WL - OFF_WH) * 2);

    float acc[2][4][4] = {};
    #pragma unroll
    for (int k16 = 0; k16 < 4; k16++) {
        const uint32_t kb = (uint32_t)(k16 * 32);
        uint32_t ah[2][4], al[2][4];
        ldsm_x4(ah[0], a_addr0 + kb);
        ldsm_x4(ah[1], a_addr0 + (uint32_t)(16 * LDA_S * 2) + kb);
        ldsm_x4(al[0], a_addr0 + ALO_B + kb);
        ldsm_x4(al[1], a_addr0 + ALO_B + (uint32_t)(16 * LDA_S * 2) + kb);
        uint32_t bh[2][4], bl[2][4];
        ldsm_x4(bh[0], b_addr0 + kb);
        ldsm_x4(bh[1], b_addr0 + (uint32_t)(16 * LDA_S * 2) + kb);
        ldsm_x4(bl[0], b_addr0 + WLO_B + kb);
        ldsm_x4(bl[1], b_addr0 + WLO_B + (uint32_t)(16 * LDA_S * 2) + kb);
        #pragma unroll
        for (int mi = 0; mi < 2; mi++) {
            #pragma unroll
            for (int nj = 0; nj < 4; nj++) {
                const uint32_t* bph = &bh[nj >> 1][(nj & 1) * 2];
                const uint32_t* bpl = &bl[nj >> 1][(nj & 1) * 2];
                mma16816(acc[mi][nj], ah[mi], bph);
                mma16816(acc[mi][nj], ah[mi], bpl);
                mma16816(acc[mi][nj], al[mi], bph);
            }
        }
    }

    __syncthreads();
    uint32_t* ps = (uint32_t*)sm;
    const int mbase = wm * 32 + (lane >> 2);
    const int tbase = wn * 32 + (lane & 3) * 2;
    #pragma unroll
    for (int mi = 0; mi < 2; mi++) {
        #pragma unroll
        for (int nj = 0; nj < 4; nj++) {
            int tt = tbase + nj * 8;
            float bb0 = BM[c * 512 + n0 + tt];
            float bb1 = BM[c * 512 + n0 + tt + 1];
            #pragma unroll
            for (int e = 0; e < 4; e++) {
                int mm = mbase + mi * 16 + ((e >> 1) ? 8 : 0);
                int tc2 = tt + (e & 1);
                ps[tc2 * 132 + mm] = pack_hilo(acc[mi][nj][e] + ((e & 1) ? bb1 : bb0));
            }
        }
    }
    __syncthreads();

    #pragma unroll
    for (int it = 0; it < 8; it++) {
        int u = tid + it * 256;
        int st = u >> 5, g = u & 31;
        int ml = g * 4;
        uint32_t p0 = ps[st * 132 + ml + 0];
        uint32_t p1 = ps[st * 132 + ml + 1];
        uint32_t p2 = ps[st * 132 + ml + 2];
        uint32_t p3 = ps[st * 132 + ml + 3];
        uint32_t hi01 = (p0 & 0xffffu) | (p1 << 16);
        uint32_t hi23 = (p2 & 0xffffu) | (p3 << 16);
        uint32_t lo01 = (p0 >> 16) | (p1 & 0xffff0000u);
        uint32_t lo23 = (p2 >> 16) | (p3 & 0xffff0000u);
        int m = m0 + ml;
        int b = m / 160, l = m % 160;
        size_t base = ((size_t)((b * 8 + c) * 64 + st) * 16 + r) * 160 + l;
        *(uint2*)&Y[base]            = make_uint2(hi01, hi23);
        *(uint2*)&Y[base + 8 * 160]  = make_uint2(lo01, lo23);
    }
}

// ------------------------------------------------------------------------------
// Tensor-core scores (unchanged from R10/R11).
__global__ void __launch_bounds__(128) scores_tc(
    const __nv_bfloat16* __restrict__ Y1, const __nv_bfloat16* __restrict__ Y0,
    const float* __restrict__ wbo, float* __restrict__ SC)
{
    __shared__ __nv_bfloat16 SB[2][2][128*40];
    __shared__ float swb[64];
    const int tid = threadIdx.x;
    const int warp = tid >> 5, lane = tid & 31;
    const int qt = blockIdx.x, kt = blockIdx.y;
    const int b = blockIdx.z >> 3, c = blockIdx.z & 7;
    const int qoff = (warp >> 1) * 16, koff = (warp & 1) * 16;
    if (tid < 64) swb[tid] = wbo[c * 64 + tid];

    const uint32_t sbb = smem_u32(SB);
    const int t4 = lane >> 3, rr = lane & 7;
    const int lrow = ((t4 & 2) ? 8 : 0) + rr;
    const uint32_t aoff = (uint32_t)((lrow * 40 + qoff + (t4 & 1) * 8) * 2);
    const uint32_t boff = (uint32_t)((lrow * 40 + koff + (t4 & 1) * 8) * 2);

    const int su   = tid;
    const int cbase = (b * 8 + c) * 1024;

    auto issue = [&](int oct, int buf) {
        const int sbase = cbase + oct * 128;
        #pragma unroll
        for (int it = 0; it < 8; it++) {
            int u = su + it * 128;
            int half = u >> 9, v = u & 511;
            int row = v >> 2, ch = v & 3;
            const __nv_bfloat16* src = (half ? Y0 : Y1)
                + (size_t)(sbase + row) * 160 + (half ? kt : qt) * 32 + ch * 8;
            uint32_t dst = sbb + (uint32_t)(((buf * 2 + half) * 5120 + row * 40 + ch * 8) * 2);
            cp16(dst, src);
        }
        asm volatile("cp.async.commit_group;" ::: "memory");
    };

    issue(0, 0);

    float num[2][4] = {}, den[2][4] = {};
    for (int oct = 0; oct < 8; oct++) {
        const int buf = oct & 1;
        if (oct < 7) {
            issue(oct + 1, buf ^ 1);
            asm volatile("cp.async.wait_group 1;" ::: "memory");
        } else {
            asm volatile("cp.async.wait_group 0;" ::: "memory");
        }
        __syncthreads();
        const uint32_t s1b = sbb + (uint32_t)(buf * 2 * 10240);
        const uint32_t s0b = s1b + 10240;
        #pragma unroll
        for (int st = 0; st < 8; st++) {
            const uint32_t tb = (uint32_t)(st * 1280);
            uint32_t a[4], bv[4];
            ldsm_x4t(a,  s1b + tb + aoff);
            ldsm_x4t(bv, s0b + tb + boff);
            float z0[4], z1[4];
            mma1688_z  (z0, a[0], a[1], bv[0]);
            mma1688_acc(z0, a[0], a[1], bv[2]);
            mma1688_acc(z0, a[2], a[3], bv[0]);
            mma1688_z  (z1, a[0], a[1], bv[1]);
            mma1688_acc(z1, a[0], a[1], bv[3]);
            mma1688_acc(z1, a[2], a[3], bv[1]);
            const float wb = swb[oct * 8 + st];
            #pragma unroll
            for (int e = 0; e < 4; e++) {
                {
                    float az = fabsf(z0[e]);
                    den[0][e] += az;
                    float s;
                    asm("sqrt.approx.f32 %0, %1;" : "=f"(s) : "f"(az));
                    uint32_t sb2 = (__float_as_uint(s) & 0x7fffffffu)
                                 | (__float_as_uint(z0[e]) & 0x80000000u);
                    num[0][e] = fmaf(wb, __uint_as_float(sb2), num[0][e]);
                }
                {
                    float az = fabsf(z1[e]);
                    den[1][e] += az;
                    float s;
                    asm("sqrt.approx.f32 %0, %1;" : "=f"(s) : "f"(az));
                    uint32_t sb2 = (__float_as_uint(s) & 0x7fffffffu)
                                 | (__float_as_uint(z1[e]) & 0x80000000u);
                    num[1][e] = fmaf(wb, __uint_as_float(sb2), num[1][e]);
                }
            }
        }
        __syncthreads();
    }

    const int q = qt*32 + qoff + (lane >> 2);
    const int k = kt*32 + koff + (lane & 3)*2;
    float* p0 = SC + (size_t)c * SC_PLANE + (size_t)(b*160 + q)*160 + k;
    *(float2*)(p0)             = make_float2(num[0][0] * rsqrtf(fmaxf(den[0][0], 1e-24f)),
                                             num[0][1] * rsqrtf(fmaxf(den[0][1], 1e-24f)));
    *(float2*)(p0 + 8)         = make_float2(num[1][0] * rsqrtf(fmaxf(den[1][0], 1e-24f)),
                                             num[1][1] * rsqrtf(fmaxf(den[1][1], 1e-24f)));
    *(float2*)(p0 + 8*160)     = make_float2(num[0][2] * rsqrtf(fmaxf(den[0][2], 1e-24f)),
                                             num[0][3] * rsqrtf(fmaxf(den[0][3], 1e-24f)));
    *(float2*)(p0 + 8*160 + 8) = make_float2(num[1][2] * rsqrtf(fmaxf(den[1][2], 1e-24f)),
                                             num[1][3] * rsqrtf(fmaxf(den[1][3], 1e-24f)));
}

// ------------------------------------------------------------------------------
__global__ void __launch_bounds__(192) softmax_kernel(float* __restrict__ sc)
{
    const int row = blockIdx.x;
    float* p = sc + (size_t)row*160;
    const int t = threadIdx.x;
    __shared__ float red[6], red2[6];
    float x = -3.0e38f;
    if (t < 160) {
        x = 0.f;
        #pragma unroll
        for (int i = 0; i < 8; i++) x += p[(size_t)i*SC_PLANE + t];
    }
    float v = x;
    #pragma unroll
    for (int o = 16; o; o >>= 1) v = fmaxf(v, __shfl_xor_sync(0xffffffffu, v, o));
    if ((t & 31) == 0) red[t >> 5] = v;
    __syncthreads();
    float m = red[0];
    #pragma unroll
    for (int i = 1; i < 6; i++) m = fmaxf(m, red[i]);
    float e = (t < 160) ? expf(x - m) : 0.f;
    float sv = e;
    #pragma unroll
    for (int o = 16; o; o >>= 1) sv += __shfl_xor_sync(0xffffffffu, sv, o);
    if ((t & 31) == 0) red2[t >> 5] = sv;
    __syncthreads();
    float ssum = 0.f;
    #pragma unroll
    for (int i = 0; i < 6; i++) ssum += red2[i];
    if (t < 160) p[t] = e / ssum;
}

// ------------------------------------------------------------------------------
// Tensor-core attv; output now bf16 hi/lo planes (for bf16 gemm3).
__global__ void __launch_bounds__(128) attv_tc_kernel(
    const float* __restrict__ att, const float* __restrict__ vv,
    __nv_bfloat16* __restrict__ scr)
{
    __shared__ __nv_bfloat16 Ah[32*40], Al[32*40], Bh[32*72], Bl[32*72];
    __shared__ float ts[64*33];
    const int tid = threadIdx.x;
    const int warp = tid >> 5, lane = tid & 31;
    const int q0 = blockIdx.x * 32, h0 = blockIdx.y * 64, b = blockIdx.z;
    const int wm = warp & 1, wn = warp >> 1;
    const float* A = att + (size_t)b * 25600;
    const float* V = vv + (size_t)b * 81920;
    const uint32_t ahb = smem_u32(Ah), alb = smem_u32(Al);
    const uint32_t bhb = smem_u32(Bh), blb = smem_u32(Bl);
    const uint32_t a_off = (uint32_t)(((wm * 16 + (lane & 15)) * 40 + (lane >> 4) * 8) * 2);
    const int tb_row = ((lane >> 3) & 1) * 8 + (lane & 7);
    const int tb_col = wn * 32 + (lane >> 4) * 8;

    float acc[4][4] = {};
    for (int kc = 0; kc < 5; kc++) {
        const int k0 = kc * 32;
        __syncthreads();
        #pragma unroll
        for (int it = 0; it < 2; it++) {
            int u = tid + it * 128;
            int row = u >> 3, c4 = (u & 7) * 4;
            float4 v4 = *(const float4*)(A + (q0 + row) * 160 + k0 + c4);
            split_store(Ah, Al, row * 40 + c4, v4);
        }
        #pragma unroll
        for (int it = 0; it < 4; it++) {
            int u = tid + it * 128;
            int row = u >> 4, c4 = (u & 15) * 4;
            float4 v4 = *(const float4*)(V + (k0 + row) * 512 + h0 + c4);
            split_store(Bh, Bl, row * 72 + c4, v4);
        }
        __syncthreads();
        #pragma unroll
        for (int k16 = 0; k16 < 2; k16++) {
            uint32_t ah[4], al[4];
            ldsm_x4(ah, ahb + a_off + k16 * 32);
            ldsm_x4(al, alb + a_off + k16 * 32);
            uint32_t bh[2][4], bl[2][4];
            const uint32_t bo = (uint32_t)(((k16 * 16 + tb_row) * 72 + tb_col) * 2);
            ldsm_x4t(bh[0], bhb + bo);
            ldsm_x4t(bh[1], bhb + bo + 32);
            ldsm_x4t(bl[0], blb + bo);
            ldsm_x4t(bl[1], blb + bo + 32);
            #pragma unroll
            for (int nj = 0; nj < 4; nj++) {
                const uint32_t* ph = &bh[nj >> 1][(nj & 1) * 2];
                const uint32_t* pl = &bl[nj >> 1][(nj & 1) * 2];
                mma16816(acc[nj], ah, ph);
                mma16816(acc[nj], ah, pl);
                mma16816(acc[nj], al, ph);
            }
        }
    }
    __syncthreads();
    const int mr = wm * 16 + (lane >> 2);
    const int nc = wn * 32 + (lane & 3) * 2;
    #pragma unroll
    for (int nj = 0; nj < 4; nj++) {
        int h = nc + nj * 8;
        ts[h * 33 + mr]           = acc[nj][0];
        ts[(h + 1) * 33 + mr]     = acc[nj][1];
        ts[h * 33 + mr + 8]       = acc[nj][2];
        ts[(h + 1) * 33 + mr + 8] = acc[nj][3];
    }
    __syncthreads();
    const int h = tid >> 1, qh = (tid & 1) * 16;
    const float* tsr = ts + h * 33 + qh;
    uint32_t hw[8], lw[8];
    #pragma unroll
    for (int i = 0; i < 8; i++)
        split_pair(tsr[2*i], tsr[2*i + 1], hw[i], lw[i]);
    size_t off = (size_t)b * 81920 + (size_t)(h0 + h) * 160 + q0 + qh;
    *(uint4*)&scr[off]          = make_uint4(hw[0], hw[1], hw[2], hw[3]);
    *(uint4*)&scr[off + 8]      = make_uint4(hw[4], hw[5], hw[6], hw[7]);
    *(uint4*)&scr[XPLANE + off]     = make_uint4(lw[0], lw[1], lw[2], lw[3]);
    *(uint4*)&scr[XPLANE + off + 8] = make_uint4(lw[4], lw[5], lw[6], lw[7]);
}

// ------------------------------------------------------------------------------
extern "C" void kernel_launch(void* const* d_in, const int* in_sizes, int n_in,
                              void* d_out, int out_size)
{
    (void)in_sizes; (void)n_in; (void)out_size;
    const float* v    = (const float*)d_in[0];
    const float* kin  = (const float*)d_in[1];
    const float* qin  = (const float*)d_in[2];
    const float* w_v  = (const float*)d_in[3];  const float* b_v = (const float*)d_in[4];
    const float* w_k  = (const float*)d_in[5];  const float* b_k = (const float*)d_in[6];
    const float* w_q  = (const float*)d_in[7];  const float* b_q = (const float*)d_in[8];
    const float* w0   = (const float*)d_in[9];  const float* b0  = (const float*)d_in[10];
    const float* w1   = (const float*)d_in[11]; const float* b1  = (const float*)d_in[12];
    const float* wm0  = (const float*)d_in[13]; const float* bm0 = (const float*)d_in[14];
    const float* wm1  = (const float*)d_in[15]; const float* bm1 = (const float*)d_in[16];
    const float* w_bo = (const float*)d_in[17];
    const float* w_m  = (const float*)d_in[19]; const float* b_m = (const float*)d_in[20];
    float* out = (float*)d_out;

    float *vv, *bc, *sc;
    __nv_bfloat16 *vs, *ks, *qs, *wvs, *wml, *w0k, *w1q, *x0, *x1, *wms, *y0, *y1, *scr;
    cudaGetSymbolAddress((void**)&vv,  g_vv);
    cudaGetSymbolAddress((void**)&vs,  g_vs);
    cudaGetSymbolAddress((void**)&ks,  g_ks);
    cudaGetSymbolAddress((void**)&qs,  g_qs);
    cudaGetSymbolAddress((void**)&wvs, g_wvs);
    cudaGetSymbolAddress((void**)&wml, g_wml);
    cudaGetSymbolAddress((void**)&w0k, g_w0k);
    cudaGetSymbolAddress((void**)&w1q, g_w1q);
    cudaGetSymbolAddress((void**)&bc,  g_bc);
    cudaGetSymbolAddress((void**)&x0,  g_x0);
    cudaGetSymbolAddress((void**)&x1,  g_x1);
    cudaGetSymbolAddress((void**)&wms, g_wms);
    cudaGetSymbolAddress((void**)&y0,  g_y0);
    cudaGetSymbolAddress((void**)&y1,  g_y1);
    cudaGetSymbolAddress((void**)&sc,  g_sc);
    cudaGetSymbolAddress((void**)&scr, g_scr);

    static int smem_set = 0;
    if (!smem_set) {
        cudaFuncSetAttribute(bf16_gemm_kernel,
                             cudaFuncAttributeMaxDynamicSharedMemorySize, G_SMEM);
        cudaFuncSetAttribute(merge_tc_kernel,
                             cudaFuncAttributeMaxDynamicSharedMemorySize, HM_SMEM_BYTES);
        cudaFuncSetAttribute(prep_hmma_kernel,
                             cudaFuncAttributeMaxDynamicSharedMemorySize, HM_SMEM_BYTES);
        smem_set = 1;
    }

    // preprocessing: splits + weight composition + composed biases
    split5_kernel<<<dim3(640, 5), 256>>>(v, kin, qin, w_v, w_m, vs, ks, qs, wvs, wml);
    prep_hmma_kernel<<<dim3(4, 8, 2), 256, HM_SMEM_BYTES>>>(w0, w_k, w0k, w1, w_q, w1q);
    bias_comp_kernel<<<dim3(64, 2), 256>>>(w0, b_k, b0, w1, b_q, b1, bc);
    wm_split_kernel<<<dim3(128, 2), 256>>>(wm0, wm1, wms);

    // Stage 1: vv (fp32), x0/x1 (bf16 planes)
    GemmB g1;
    g1.A[0] = vs; g1.Astride[0] = XPLANE; g1.W[0] = wvs; g1.Wstride[0] = WPL;
    g1.bias[0] = b_v;      g1.C[0] = vv;         g1.pack[0] = 0;
    g1.A[1] = ks; g1.Astride[1] = XPLANE; g1.W[1] = w0k; g1.Wstride[1] = WPL;
    g1.bias[1] = bc;       g1.C[1] = (float*)x0; g1.pack[1] = 1;
    g1.A[2] = qs; g1.Astride[2] = XPLANE; g1.W[2] = w1q; g1.Wstride[2] = WPL;
    g1.bias[2] = bc + 512; g1.C[2] = (float*)x1; g1.pack[2] = 1;
    bf16_gemm_kernel<<<dim3(10, 8, 3), 256, G_SMEM>>>(g1);

    MergeBatch mrg;
    mrg.X[0] = x0; mrg.WMS[0] = wms;              mrg.BM[0] = bm0; mrg.Y[0] = y0;
    mrg.X[1] = x1; mrg.WMS[1] = wms + 2*WMPLANE;  mrg.BM[1] = bm1; mrg.Y[1] = y1;
    merge_tc_kernel<<<dim3(10, 8, 16), 256, HM_SMEM_BYTES>>>(mrg);

    scores_tc<<<dim3(5, 5, 64), 128>>>(y1, y0, w_bo, sc);
    softmax_kernel<<<1280, 192>>>(sc);
    attv_tc_kernel<<<dim3(5, 8, 8), 128>>>(sc, vv, scr);

    // Stage 3: out = scr @ w_m^T + b_m  (bf16 planes in, fp32 out)
    GemmB g3;
    g3.A[0] = scr; g3.Astride[0] = XPLANE; g3.W[0] = wml; g3.Wstride[0] = WPL;
    g3.bias[0] = b_m; g3.C[0] = out; g3.pack[0] = 0;
    g3.A[1] = g3.A[0]; g3.Astride[1] = XPLANE; g3.W[1] = wml; g3.Wstride[1] = WPL;
    g3.bias[1] = b_m; g3.C[1] = out; g3.pack[1] = 0;
    g3.A[2] = g3.A[0]; g3.Astride[2] = XPLANE; g3.W[2] = wml; g3.Wstride[2] = WPL;
    g3.bias[2] = b_m; g3.C[2] = out; g3.pack[2] = 0;
    bf16_gemm_kernel<<<dim3(10, 8, 1), 256, G_SMEM>>>(g3);
}

// round 13
// speedup vs baseline: 1.0714x; 1.0714x over previous
#include <cuda_runtime.h>
#include <cuda_bf16.h>
#include <cstdint>

// Problem constants (fixed shapes from the reference)
#define NB_B 8
#define NB_L 160
#define NB_H 512
#define NB_C 8
#define NB_S 64
#define NB_R 8
#define NB_BL (NB_B*NB_L)   // 1280
#define SC_PLANE (NB_B*NB_L*NB_L)   // 204800
#define XPLANE (NB_BL*NB_H)         // 655360
#define WMPLANE (NB_C*NB_H*NB_S)    // 262144

// ---------------- scratch (device globals: no runtime allocation) -------------
__device__ float g_vv [NB_BL*NB_H];
__device__ float g_w0k[NB_H*NB_H];
__device__ float g_w1q[NB_H*NB_H];
__device__ float g_bc [2*NB_H];
__device__ __nv_bfloat16 g_x0 [2*XPLANE];   // hi plane | lo plane
__device__ __nv_bfloat16 g_x1 [2*XPLANE];
__device__ __nv_bfloat16 g_wms[2][2*WMPLANE]; // [tensor][hi|lo]
// Y layout: [b][c][s(64)][r(16: 8 hi | 8 lo)][l(160)] bf16
__device__ __nv_bfloat16 g_y0 [NB_B*NB_C*NB_S*16*NB_L];
__device__ __nv_bfloat16 g_y1 [NB_B*NB_C*NB_S*16*NB_L];
__device__ float g_sc [8*SC_PLANE];
__device__ float g_scr[NB_BL*NB_H];

// ======================= mma.sync helpers (sm_80+ path) =======================
__device__ __forceinline__ uint32_t smem_u32(const void* p) {
    uint32_t a;
    asm("{ .reg .u64 t; cvta.to.shared.u64 t, %1; cvt.u32.u64 %0, t; }"
        : "=r"(a) : "l"(p));
    return a;
}
__device__ __forceinline__ void mma16816(float* d, const uint32_t* a, const uint32_t* b) {
    asm volatile(
        "mma.sync.aligned.m16n8k16.row.col.f32.bf16.bf16.f32 "
        "{%0,%1,%2,%3}, {%4,%5,%6,%7}, {%8,%9}, {%0,%1,%2,%3};"
        : "+f"(d[0]), "+f"(d[1]), "+f"(d[2]), "+f"(d[3])
        : "r"(a[0]), "r"(a[1]), "r"(a[2]), "r"(a[3]), "r"(b[0]), "r"(b[1]));
}
__device__ __forceinline__ void ldsm_x4(uint32_t* r, uint32_t addr) {
    asm volatile("ldmatrix.sync.aligned.m8n8.x4.shared.b16 {%0,%1,%2,%3}, [%4];"
        : "=r"(r[0]), "=r"(r[1]), "=r"(r[2]), "=r"(r[3]) : "r"(addr));
}
__device__ __forceinline__ void ldsm_x4t(uint32_t* r, uint32_t addr) {
    asm volatile("ldmatrix.sync.aligned.m8n8.x4.trans.shared.b16 {%0,%1,%2,%3}, [%4];"
        : "=r"(r[0]), "=r"(r[1]), "=r"(r[2]), "=r"(r[3]) : "r"(addr));
}
__device__ __forceinline__ void mma1688_z(float* d, uint32_t a0, uint32_t a1, uint32_t b) {
    asm volatile(
        "mma.sync.aligned.m16n8k8.row.col.f32.bf16.bf16.f32 "
        "{%0,%1,%2,%3}, {%4,%5}, {%6}, {%7,%8,%9,%10};"
        : "=f"(d[0]), "=f"(d[1]), "=f"(d[2]), "=f"(d[3])
        : "r"(a0), "r"(a1), "r"(b), "f"(0.f), "f"(0.f), "f"(0.f), "f"(0.f));
}
__device__ __forceinline__ void mma1688_acc(float* d, uint32_t a0, uint32_t a1, uint32_t b) {
    asm volatile(
        "mma.sync.aligned.m16n8k8.row.col.f32.bf16.bf16.f32 "
        "{%0,%1,%2,%3}, {%4,%5}, {%6}, {%0,%1,%2,%3};"
        : "+f"(d[0]), "+f"(d[1]), "+f"(d[2]), "+f"(d[3])
        : "r"(a0), "r"(a1), "r"(b));
}
__device__ __forceinline__ void cp16(uint32_t dst, const void* src) {
    asm volatile("cp.async.cg.shared.global [%0], [%1], 16;" :: "r"(dst), "l"(src));
}
__device__ __forceinline__ void cp8(uint32_t dst, const void* src) {
    asm volatile("cp.async.ca.shared.global [%0], [%1], 8;" :: "r"(dst), "l"(src));
}
__device__ __forceinline__ void split_store(__nv_bfloat16* smh, __nv_bfloat16* sml,
                                            int off, float4 v) {
    __nv_bfloat162 h01 = __floats2bfloat162_rn(v.x, v.y);
    __nv_bfloat162 h23 = __floats2bfloat162_rn(v.z, v.w);
    float2 f01 = __bfloat1622float2(h01);
    float2 f23 = __bfloat1622float2(h23);
    __nv_bfloat162 l01 = __floats2bfloat162_rn(v.x - f01.x, v.y - f01.y);
    __nv_bfloat162 l23 = __floats2bfloat162_rn(v.z - f23.x, v.w - f23.y);
    *(uint2*)&smh[off] = make_uint2(*(uint32_t*)&h01, *(uint32_t*)&h23);
    *(uint2*)&sml[off] = make_uint2(*(uint32_t*)&l01, *(uint32_t*)&l23);
}
__device__ __forceinline__ uint32_t pack_hilo(float v) {
    __nv_bfloat16 hi = __float2bfloat16(v);
    __nv_bfloat16 lo = __float2bfloat16(v - __bfloat162float(hi));
    return (uint32_t)*(uint16_t*)&hi | ((uint32_t)*(uint16_t*)&lo << 16);
}
__device__ __forceinline__ void split_pair(float a, float b, uint32_t& h, uint32_t& l) {
    __nv_bfloat162 hp = __floats2bfloat162_rn(a, b);
    float2 f = __bfloat1622float2(hp);
    __nv_bfloat162 lp = __floats2bfloat162_rn(a - f.x, b - f.y);
    h = *(uint32_t*)&hp;
    l = *(uint32_t*)&lp;
}

// ================= bf16-split tensor-core GEMM: C = A @ W^T + bias ===========
// pack[z] != 0 -> store bf16 hi plane at C, lo plane at C + XPLANE.
struct GemmBatch {
    const float* A[3]; const float* W[3]; const float* bias[3]; float* C[3];
    int pack[3];
};

#define LDA_S 72
#define OFF_AH 0
#define OFF_AL (128*LDA_S)
#define OFF_WH (256*LDA_S)
#define OFF_WL (320*LDA_S)
#define HM_SMEM_BYTES (384*LDA_S*2)   // 55296

__global__ void __launch_bounds__(256) hmma_gemm_kernel(GemmBatch gb)
{
    extern __shared__ __nv_bfloat16 sm[];
    const int tid  = threadIdx.x;
    const int wid  = tid >> 5, lane = tid & 31;
    const int z = blockIdx.z;
    const float* A    = gb.A[z];
    const float* W    = gb.W[z];
    const float* bias = gb.bias[z];
    float*       C    = gb.C[z];
    const int m0 = blockIdx.x * 128;
    const int n0 = blockIdx.y * 64;
    const int wm = wid & 3, wn = wid >> 2;
    const uint32_t sb = smem_u32(sm);

    float acc[2][4][4] = {};

    const int a_row = wm * 32 + (lane & 15);
    const uint32_t a_addr0 = sb + (uint32_t)((OFF_AH + a_row * LDA_S + (lane >> 4) * 8) * 2);
    const int b_row = wn * 32 + ((lane >> 4) & 1) * 8 + (lane & 7);
    const uint32_t b_addr0 = sb + (uint32_t)((OFF_WH + b_row * LDA_S + ((lane >> 3) & 1) * 8) * 2);
    const uint32_t ALO_B = (uint32_t)((OFF_AL - OFF_AH) * 2);
    const uint32_t WLO_B = (uint32_t)((OFF_WL - OFF_WH) * 2);

    const int arow = tid >> 4, akg = (tid & 15) << 2;
    float4 pa[8], pw[4];
    #pragma unroll
    for (int it = 0; it < 8; it++)
        pa[it] = *(const float4*)(A + (m0 + arow + it * 16) * 512 + akg);
    #pragma unroll
    for (int it = 0; it < 4; it++)
        pw[it] = *(const float4*)(W + (n0 + arow + it * 16) * 512 + akg);

    for (int kc = 0; kc < 8; kc++) {
        __syncthreads();
        #pragma unroll
        for (int it = 0; it < 8; it++)
            split_store(sm + OFF_AH, sm + OFF_AL, (arow + it * 16) * LDA_S + akg, pa[it]);
        #pragma unroll
        for (int it = 0; it < 4; it++)
            split_store(sm + OFF_WH, sm + OFF_WL, (arow + it * 16) * LDA_S + akg, pw[it]);
        __syncthreads();

        if (kc < 7) {
            const int kb2 = (kc + 1) * 64;
            #pragma unroll
            for (int it = 0; it < 8; it++)
                pa[it] = *(const float4*)(A + (m0 + arow + it * 16) * 512 + kb2 + akg);
            #pragma unroll
            for (int it = 0; it < 4; it++)
                pw[it] = *(const float4*)(W + (n0 + arow + it * 16) * 512 + kb2 + akg);
        }

        #pragma unroll
        for (int k16 = 0; k16 < 4; k16++) {
            const uint32_t kb = (uint32_t)(k16 * 32);
            uint32_t ah[2][4], al[2][4];
            ldsm_x4(ah[0], a_addr0 + kb);
            ldsm_x4(ah[1], a_addr0 + (uint32_t)(16 * LDA_S * 2) + kb);
            ldsm_x4(al[0], a_addr0 + ALO_B + kb);
            ldsm_x4(al[1], a_addr0 + ALO_B + (uint32_t)(16 * LDA_S * 2) + kb);
            uint32_t bh[2][4], bl[2][4];
            ldsm_x4(bh[0], b_addr0 + kb);
            ldsm_x4(bh[1], b_addr0 + (uint32_t)(16 * LDA_S * 2) + kb);
            ldsm_x4(bl[0], b_addr0 + WLO_B + kb);
            ldsm_x4(bl[1], b_addr0 + WLO_B + (uint32_t)(16 * LDA_S * 2) + kb);
            #pragma unroll
            for (int mi = 0; mi < 2; mi++) {
                #pragma unroll
                for (int nj = 0; nj < 4; nj++) {
                    const uint32_t* bph = &bh[nj >> 1][(nj & 1) * 2];
                    const uint32_t* bpl = &bl[nj >> 1][(nj & 1) * 2];
                    mma16816(acc[mi][nj], ah[mi], bph);
                    mma16816(acc[mi][nj], ah[mi], bpl);
                    mma16816(acc[mi][nj], al[mi], bph);
                }
            }
        }
    }

    const int mrow = m0 + wm * 32 + (lane >> 2);
    const int ncol = n0 + wn * 32 + (lane & 3) * 2;
    if (gb.pack[z]) {
        __nv_bfloat16* Ch = (__nv_bfloat16*)C;
        __nv_bfloat16* Cl = Ch + XPLANE;
        #pragma unroll
        for (int mi = 0; mi < 2; mi++) {
            #pragma unroll
            for (int nj = 0; nj < 4; nj++) {
                int n = ncol + nj * 8;
                float b0 = bias[n], b1 = bias[n + 1];
                int m_a = mrow + mi * 16;
                uint32_t h, l;
                split_pair(acc[mi][nj][0] + b0, acc[mi][nj][1] + b1, h, l);
                *(uint32_t*)&Ch[m_a * 512 + n] = h;
                *(uint32_t*)&Cl[m_a * 512 + n] = l;
                split_pair(acc[mi][nj][2] + b0, acc[mi][nj][3] + b1, h, l);
                *(uint32_t*)&Ch[(m_a + 8) * 512 + n] = h;
                *(uint32_t*)&Cl[(m_a + 8) * 512 + n] = l;
            }
        }
    } else {
        #pragma unroll
        for (int mi = 0; mi < 2; mi++) {
            #pragma unroll
            for (int nj = 0; nj < 4; nj++) {
                int n = ncol + nj * 8;
                float b0 = bias[n], b1 = bias[n + 1];
                int m_a = mrow + mi * 16;
                *(float2*)&C[m_a * 512 + n]       = make_float2(acc[mi][nj][0] + b0, acc[mi][nj][1] + b1);
                *(float2*)&C[(m_a + 8) * 512 + n] = make_float2(acc[mi][nj][2] + b0, acc[mi][nj][3] + b1);
            }
        }
    }
}

// ------------------------------------------------------------------------------
// Weight composition (NN GEMM) with register prefetch (unchanged from R10/R11).
__global__ void __launch_bounds__(256) prep_hmma_kernel(
    const float* __restrict__ A0, const float* __restrict__ B0, float* __restrict__ C0,
    const float* __restrict__ A1, const float* __restrict__ B1, float* __restrict__ C1)
{
    extern __shared__ __nv_bfloat16 sm[];
    const int tid  = threadIdx.x;
    const int wid  = tid >> 5, lane = tid & 31;
    const float* A = blockIdx.z ? A1 : A0;
    const float* B = blockIdx.z ? B1 : B0;
    float*       C = blockIdx.z ? C1 : C0;
    const int m0 = blockIdx.x * 128;
    const int n0 = blockIdx.y * 64;
    const int wm = wid & 3, wn = wid >> 2;
    const uint32_t sb = smem_u32(sm);

    float acc[2][4][4] = {};

    const int a_row = wm * 32 + (lane & 15);
    const uint32_t a_addr0 = sb + (uint32_t)((OFF_AH + a_row * LDA_S + (lane >> 4) * 8) * 2);
    const int tb_row = ((lane >> 3) & 1) * 8 + (lane & 7);
    const int tb_col = wn * 32 + (lane >> 4) * 8;
    const uint32_t ALO_B = (uint32_t)((OFF_AL - OFF_AH) * 2);
    const uint32_t WLO_B = (uint32_t)((OFF_WL - OFF_WH) * 2);

    const int arow = tid >> 4, akg = (tid & 15) << 2;
    float4 pa[8], pw[4];
    #pragma unroll
    for (int it = 0; it < 8; it++)
        pa[it] = *(const float4*)(A + (m0 + arow + it * 16) * 512 + akg);
    #pragma unroll
    for (int it = 0; it < 4; it++)
        pw[it] = *(const float4*)(B + (arow + it * 16) * 512 + n0 + akg);

    for (int kc = 0; kc < 8; kc++) {
        __syncthreads();
        #pragma unroll
        for (int it = 0; it < 8; it++)
            split_store(sm + OFF_AH, sm + OFF_AL, (arow + it * 16) * LDA_S + akg, pa[it]);
        #pragma unroll
        for (int it = 0; it < 4; it++)
            split_store(sm + OFF_WH, sm + OFF_WL, (arow + it * 16) * LDA_S + akg, pw[it]);
        __syncthreads();

        if (kc < 7) {
            const int kb2 = (kc + 1) * 64;
            #pragma unroll
            for (int it = 0; it < 8; it++)
                pa[it] = *(const float4*)(A + (m0 + arow + it * 16) * 512 + kb2 + akg);
            #pragma unroll
            for (int it = 0; it < 4; it++)
                pw[it] = *(const float4*)(B + (kb2 + arow + it * 16) * 512 + n0 + akg);
        }

        #pragma unroll
        for (int k16 = 0; k16 < 4; k16++) {
            const uint32_t kb = (uint32_t)(k16 * 32);
            uint32_t ah[2][4], al[2][4];
            ldsm_x4(ah[0], a_addr0 + kb);
            ldsm_x4(ah[1], a_addr0 + (uint32_t)(16 * LDA_S * 2) + kb);
            ldsm_x4(al[0], a_addr0 + ALO_B + kb);
            ldsm_x4(al[1], a_addr0 + ALO_B + (uint32_t)(16 * LDA_S * 2) + kb);
            uint32_t bh[2][4], bl[2][4];
            const uint32_t bo = sb + (uint32_t)((OFF_WH + (k16 * 16 + tb_row) * LDA_S + tb_col) * 2);
            ldsm_x4t(bh[0], bo);
            ldsm_x4t(bh[1], bo + 32);
            ldsm_x4t(bl[0], bo + WLO_B);
            ldsm_x4t(bl[1], bo + WLO_B + 32);
            #pragma unroll
            for (int mi = 0; mi < 2; mi++) {
                #pragma unroll
                for (int nj = 0; nj < 4; nj++) {
                    const uint32_t* bph = &bh[nj >> 1][(nj & 1) * 2];
                    const uint32_t* bpl = &bl[nj >> 1][(nj & 1) * 2];
                    mma16816(acc[mi][nj], ah[mi], bph);
                    mma16816(acc[mi][nj], ah[mi], bpl);
                    mma16816(acc[mi][nj], al[mi], bph);
                }
            }
        }
    }

    const int mrow = m0 + wm * 32 + (lane >> 2);
    const int ncol = n0 + wn * 32 + (lane & 3) * 2;
    #pragma unroll
    for (int mi = 0; mi < 2; mi++) {
        #pragma unroll
        for (int nj = 0; nj < 4; nj++) {
            int n = ncol + nj * 8;
            int m_a = mrow + mi * 16;
            *(float2*)&C[m_a * 512 + n]       = make_float2(acc[mi][nj][0], acc[mi][nj][1]);
            *(float2*)&C[(m_a + 8) * 512 + n] = make_float2(acc[mi][nj][2], acc[mi][nj][3]);
        }
    }
}

// ------------------------------------------------------------------------------
__global__ void __launch_bounds__(256) bias_comp_kernel(
    const float* __restrict__ w0, const float* __restrict__ bk, const float* __restrict__ b0,
    const float* __restrict__ w1, const float* __restrict__ bq, const float* __restrict__ b1,
    float* __restrict__ bc)
{
    const int z = blockIdx.y;
    const float* W  = z ? w1 : w0;
    const float* bi = z ? bq : bk;
    const float* bo = z ? b1 : b0;
    const int warp = threadIdx.x >> 5, lane = threadIdx.x & 31;
    const int n = blockIdx.x * 8 + warp;
    const float* row = W + n * 512;
    float s = 0.f;
    #pragma unroll 4
    for (int h = lane; h < 512; h += 32) s = fmaf(row[h], bi[h], s);
    #pragma unroll
    for (int o = 16; o; o >>= 1) s += __shfl_xor_sync(0xffffffffu, s, o);
    if (lane == 0) bc[z * 512 + n] = s + bo[n];
}

// ------------------------------------------------------------------------------
// wm split: fp32 merge weights -> bf16 hi/lo planes, 16B stores.
__global__ void __launch_bounds__(256) wm_split_kernel(
    const float* __restrict__ wm0, const float* __restrict__ wm1,
    __nv_bfloat16* __restrict__ wms)
{
    const int t = blockIdx.y;
    const float* src = t ? wm1 : wm0;
    __nv_bfloat16* dh = wms + (size_t)t * 2 * WMPLANE;
    __nv_bfloat16* dl = dh + WMPLANE;
    const int i8 = (blockIdx.x * 256 + threadIdx.x) * 8;   // 8 floats per thread
    float4 v0 = *(const float4*)(src + i8);
    float4 v1 = *(const float4*)(src + i8 + 4);
    uint32_t h[4], l[4];
    split_pair(v0.x, v0.y, h[0], l[0]);
    split_pair(v0.z, v0.w, h[1], l[1]);
    split_pair(v1.x, v1.y, h[2], l[2]);
    split_pair(v1.z, v1.w, h[3], l[3]);
    *(uint4*)&dh[i8] = make_uint4(h[0], h[1], h[2], h[3]);
    *(uint4*)&dl[i8] = make_uint4(l[0], l[1], l[2], l[3]);
}

// ------------------------------------------------------------------------------
// Tensor-core merge (R11: cp.async pre-split planes, stride 72).
struct MergeBatch {
    const __nv_bfloat16* X[2];
    const __nv_bfloat16* WMS[2];
    const float* BM[2];
    __nv_bfloat16* Y[2];
};

__global__ void __launch_bounds__(256) merge_tc_kernel(MergeBatch mb)
{
    extern __shared__ __nv_bfloat16 sm[];
    const int tid  = threadIdx.x;
    const int wid  = tid >> 5, lane = tid & 31;
    const int zz = blockIdx.z;
    const int tensor = zz >> 3, c = zz & 7;
    const __nv_bfloat16* X   = mb.X[tensor];
    const __nv_bfloat16* WMS = mb.WMS[tensor];
    const float* BM = mb.BM[tensor];
    __nv_bfloat16* Y = mb.Y[tensor];
    const int m0 = blockIdx.x * 128;
    const int r  = blockIdx.y;
    const int n0 = r * 64;
    const int wm = wid & 3, wn = wid >> 2;
    const uint32_t sb = smem_u32(sm);

    #pragma unroll
    for (int it = 0; it < 16; it++) {
        int u = tid + it * 256;
        int plane = u >> 11, v = u & 2047;
        int row = v >> 4, g = v & 15;
        const __nv_bfloat16* src = X + plane * XPLANE
            + (size_t)(m0 + row) * 512 + c * 64 + g * 4;
        uint32_t dst = sb + (uint32_t)(((plane ? OFF_AL : OFF_AH) + row * LDA_S + g * 4) * 2);
        cp8(dst, src);
    }
    #pragma unroll
    for (int it = 0; it < 8; it++) {
        int u = tid + it * 256;
        int plane = u >> 10, v = u & 1023;
        int row = v >> 4, g = v & 15;
        const __nv_bfloat16* src = WMS + plane * WMPLANE
            + (size_t)(c * 512 + n0 + row) * 64 + g * 4;
        uint32_t dst = sb + (uint32_t)(((plane ? OFF_WL : OFF_WH) + row * LDA_S + g * 4) * 2);
        cp8(dst, src);
    }
    asm volatile("cp.async.commit_group;" ::: "memory");
    asm volatile("cp.async.wait_group 0;" ::: "memory");
    __syncthreads();

    const int a_row = wm * 32 + (lane & 15);
    const uint32_t a_addr0 = sb + (uint32_t)((OFF_AH + a_row * LDA_S + (lane >> 4) * 8) * 2);
    const int b_row = wn * 32 + ((lane >> 4) & 1) * 8 + (lane & 7);
    const uint32_t b_addr0 = sb + (uint32_t)((OFF_WH + b_row * LDA_S + ((lane >> 3) & 1) * 8) * 2);
    const uint32_t ALO_B = (uint32_t)((OFF_AL - OFF_AH) * 2);
    const uint32_t WLO_B = (uint32_t)((OFF_WL - OFF_WH) * 2);

    float acc[2][4][4] = {};
    #pragma unroll
    for (int k16 = 0; k16 < 4; k16++) {
        const uint32_t kb = (uint32_t)(k16 * 32);
        uint32_t ah[2][4], al[2][4];
        ldsm_x4(ah[0], a_addr0 + kb);
        ldsm_x4(ah[1], a_addr0 + (uint32_t)(16 * LDA_S * 2) + kb);
        ldsm_x4(al[0], a_addr0 + ALO_B + kb);
        ldsm_x4(al[1], a_addr0 + ALO_B + (uint32_t)(16 * LDA_S * 2) + kb);
        uint32_t bh[2][4], bl[2][4];
        ldsm_x4(bh[0], b_addr0 + kb);
        ldsm_x4(bh[1], b_addr0 + (uint32_t)(16 * LDA_S * 2) + kb);
        ldsm_x4(bl[0], b_addr0 + WLO_B + kb);
        ldsm_x4(bl[1], b_addr0 + WLO_B + (uint32_t)(16 * LDA_S * 2) + kb);
        #pragma unroll
        for (int mi = 0; mi < 2; mi++) {
            #pragma unroll
            for (int nj = 0; nj < 4; nj++) {
                const uint32_t* bph = &bh[nj >> 1][(nj & 1) * 2];
                const uint32_t* bpl = &bl[nj >> 1][(nj & 1) * 2];
                mma16816(acc[mi][nj], ah[mi], bph);
                mma16816(acc[mi][nj], ah[mi], bpl);
                mma16816(acc[mi][nj], al[mi], bph);
            }
        }
    }

    __syncthreads();
    uint32_t* ps = (uint32_t*)sm;
    const int mbase = wm * 32 + (lane >> 2);
    const int tbase = wn * 32 + (lane & 3) * 2;
    #pragma unroll
    for (int mi = 0; mi < 2; mi++) {
        #pragma unroll
        for (int nj = 0; nj < 4; nj++) {
            int tt = tbase + nj * 8;
            float bb0 = BM[c * 512 + n0 + tt];
            float bb1 = BM[c * 512 + n0 + tt + 1];
            #pragma unroll
            for (int e = 0; e < 4; e++) {
                int mm = mbase + mi * 16 + ((e >> 1) ? 8 : 0);
                int tc2 = tt + (e & 1);
                ps[tc2 * 132 + mm] = pack_hilo(acc[mi][nj][e] + ((e & 1) ? bb1 : bb0));
            }
        }
    }
    __syncthreads();

    #pragma unroll
    for (int it = 0; it < 8; it++) {
        int u = tid + it * 256;
        int st = u >> 5, g = u & 31;
        int ml = g * 4;
        uint32_t p0 = ps[st * 132 + ml + 0];
        uint32_t p1 = ps[st * 132 + ml + 1];
        uint32_t p2 = ps[st * 132 + ml + 2];
        uint32_t p3 = ps[st * 132 + ml + 3];
        uint32_t hi01 = (p0 & 0xffffu) | (p1 << 16);
        uint32_t hi23 = (p2 & 0xffffu) | (p3 << 16);
        uint32_t lo01 = (p0 >> 16) | (p1 & 0xffff0000u);
        uint32_t lo23 = (p2 >> 16) | (p3 & 0xffff0000u);
        int m = m0 + ml;
        int b = m / 160, l = m % 160;
        size_t base = ((size_t)((b * 8 + c) * 64 + st) * 16 + r) * 160 + l;
        *(uint2*)&Y[base]            = make_uint2(hi01, hi23);
        *(uint2*)&Y[base + 8 * 160]  = make_uint2(lo01, lo23);
    }
}

// ------------------------------------------------------------------------------
// Tensor-core scores (unchanged).
__global__ void __launch_bounds__(128) scores_tc(
    const __nv_bfloat16* __restrict__ Y1, const __nv_bfloat16* __restrict__ Y0,
    const float* __restrict__ wbo, float* __restrict__ SC)
{
    __shared__ __nv_bfloat16 SB[2][2][128*40];
    __shared__ float swb[64];
    const int tid = threadIdx.x;
    const int warp = tid >> 5, lane = tid & 31;
    const int qt = blockIdx.x, kt = blockIdx.y;
    const int b = blockIdx.z >> 3, c = blockIdx.z & 7;
    const int qoff = (warp >> 1) * 16, koff = (warp & 1) * 16;
    if (tid < 64) swb[tid] = wbo[c * 64 + tid];

    const uint32_t sbb = smem_u32(SB);
    const int t4 = lane >> 3, rr = lane & 7;
    const int lrow = ((t4 & 2) ? 8 : 0) + rr;
    const uint32_t aoff = (uint32_t)((lrow * 40 + qoff + (t4 & 1) * 8) * 2);
    const uint32_t boff = (uint32_t)((lrow * 40 + koff + (t4 & 1) * 8) * 2);

    const int su   = tid;
    const int cbase = (b * 8 + c) * 1024;

    auto issue = [&](int oct, int buf) {
        const int sbase = cbase + oct * 128;
        #pragma unroll
        for (int it = 0; it < 8; it++) {
            int u = su + it * 128;
            int half = u >> 9, v = u & 511;
            int row = v >> 2, ch = v & 3;
            const __nv_bfloat16* src = (half ? Y0 : Y1)
                + (size_t)(sbase + row) * 160 + (half ? kt : qt) * 32 + ch * 8;
            uint32_t dst = sbb + (uint32_t)(((buf * 2 + half) * 5120 + row * 40 + ch * 8) * 2);
            cp16(dst, src);
        }
        asm volatile("cp.async.commit_group;" ::: "memory");
    };

    issue(0, 0);

    float num[2][4] = {}, den[2][4] = {};
    for (int oct = 0; oct < 8; oct++) {
        const int buf = oct & 1;
        if (oct < 7) {
            issue(oct + 1, buf ^ 1);
            asm volatile("cp.async.wait_group 1;" ::: "memory");
        } else {
            asm volatile("cp.async.wait_group 0;" ::: "memory");
        }
        __syncthreads();
        const uint32_t s1b = sbb + (uint32_t)(buf * 2 * 10240);
        const uint32_t s0b = s1b + 10240;
        #pragma unroll
        for (int st = 0; st < 8; st++) {
            const uint32_t tb = (uint32_t)(st * 1280);
            uint32_t a[4], bv[4];
            ldsm_x4t(a,  s1b + tb + aoff);
            ldsm_x4t(bv, s0b + tb + boff);
            float z0[4], z1[4];
            mma1688_z  (z0, a[0], a[1], bv[0]);
            mma1688_acc(z0, a[0], a[1], bv[2]);
            mma1688_acc(z0, a[2], a[3], bv[0]);
            mma1688_z  (z1, a[0], a[1], bv[1]);
            mma1688_acc(z1, a[0], a[1], bv[3]);
            mma1688_acc(z1, a[2], a[3], bv[1]);
            const float wb = swb[oct * 8 + st];
            #pragma unroll
            for (int e = 0; e < 4; e++) {
                {
                    float az = fabsf(z0[e]);
                    den[0][e] += az;
                    float s;
                    asm("sqrt.approx.f32 %0, %1;" : "=f"(s) : "f"(az));
                    uint32_t sb2 = (__float_as_uint(s) & 0x7fffffffu)
                                 | (__float_as_uint(z0[e]) & 0x80000000u);
                    num[0][e] = fmaf(wb, __uint_as_float(sb2), num[0][e]);
                }
                {
                    float az = fabsf(z1[e]);
                    den[1][e] += az;
                    float s;
                    asm("sqrt.approx.f32 %0, %1;" : "=f"(s) : "f"(az));
                    uint32_t sb2 = (__float_as_uint(s) & 0x7fffffffu)
                                 | (__float_as_uint(z1[e]) & 0x80000000u);
                    num[1][e] = fmaf(wb, __uint_as_float(sb2), num[1][e]);
                }
            }
        }
        __syncthreads();
    }

    const int q = qt*32 + qoff + (lane >> 2);
    const int k = kt*32 + koff + (lane & 3)*2;
    float* p0 = SC + (size_t)c * SC_PLANE + (size_t)(b*160 + q)*160 + k;
    *(float2*)(p0)             = make_float2(num[0][0] * rsqrtf(fmaxf(den[0][0], 1e-24f)),
                                             num[0][1] * rsqrtf(fmaxf(den[0][1], 1e-24f)));
    *(float2*)(p0 + 8)         = make_float2(num[1][0] * rsqrtf(fmaxf(den[1][0], 1e-24f)),
                                             num[1][1] * rsqrtf(fmaxf(den[1][1], 1e-24f)));
    *(float2*)(p0 + 8*160)     = make_float2(num[0][2] * rsqrtf(fmaxf(den[0][2], 1e-24f)),
                                             num[0][3] * rsqrtf(fmaxf(den[0][3], 1e-24f)));
    *(float2*)(p0 + 8*160 + 8) = make_float2(num[1][2] * rsqrtf(fmaxf(den[1][2], 1e-24f)),
                                             num[1][3] * rsqrtf(fmaxf(den[1][3], 1e-24f)));
}

// ------------------------------------------------------------------------------
__global__ void __launch_bounds__(192) softmax_kernel(float* __restrict__ sc)
{
    const int row = blockIdx.x;
    float* p = sc + (size_t)row*160;
    const int t = threadIdx.x;
    __shared__ float red[6], red2[6];
    float x = -3.0e38f;
    if (t < 160) {
        x = 0.f;
        #pragma unroll
        for (int i = 0; i < 8; i++) x += p[(size_t)i*SC_PLANE + t];
    }
    float v = x;
    #pragma unroll
    for (int o = 16; o; o >>= 1) v = fmaxf(v, __shfl_xor_sync(0xffffffffu, v, o));
    if ((t & 31) == 0) red[t >> 5] = v;
    __syncthreads();
    float m = red[0];
    #pragma unroll
    for (int i = 1; i < 6; i++) m = fmaxf(m, red[i]);
    float e = (t < 160) ? expf(x - m) : 0.f;
    float sv = e;
    #pragma unroll
    for (int o = 16; o; o >>= 1) sv += __shfl_xor_sync(0xffffffffu, sv, o);
    if ((t & 31) == 0) red2[t >> 5] = sv;
    __syncthreads();
    float ssum = 0.f;
    #pragma unroll
    for (int i = 0; i < 6; i++) ssum += red2[i];
    if (t < 160) p[t] = e / ssum;
}

// ------------------------------------------------------------------------------
// Tensor-core attv (NN GEMM) fused with transpose-scramble (unchanged).
__global__ void __launch_bounds__(128) attv_tc_kernel(
    const float* __restrict__ att, const float* __restrict__ vv,
    float* __restrict__ scr)
{
    __shared__ __nv_bfloat16 Ah[32*40], Al[32*40], Bh[32*72], Bl[32*72];
    __shared__ float ts[64*33];
    const int tid = threadIdx.x;
    const int warp = tid >> 5, lane = tid & 31;
    const int q0 = blockIdx.x * 32, h0 = blockIdx.y * 64, b = blockIdx.z;
    const int wm = warp & 1, wn = warp >> 1;
    const float* A = att + (size_t)b * 25600;
    const float* V = vv + (size_t)b * 81920;
    const uint32_t ahb = smem_u32(Ah), alb = smem_u32(Al);
    const uint32_t bhb = smem_u32(Bh), blb = smem_u32(Bl);
    const uint32_t a_off = (uint32_t)(((wm * 16 + (lane & 15)) * 40 + (lane >> 4) * 8) * 2);
    const int tb_row = ((lane >> 3) & 1) * 8 + (lane & 7);
    const int tb_col = wn * 32 + (lane >> 4) * 8;

    float acc[4][4] = {};
    for (int kc = 0; kc < 5; kc++) {
        const int k0 = kc * 32;
        __syncthreads();
        #pragma unroll
        for (int it = 0; it < 2; it++) {
            int u = tid + it * 128;
            int row = u >> 3, c4 = (u & 7) * 4;
            float4 v4 = *(const float4*)(A + (q0 + row) * 160 + k0 + c4);
            split_store(Ah, Al, row * 40 + c4, v4);
        }
        #pragma unroll
        for (int it = 0; it < 4; it++) {
            int u = tid + it * 128;
            int row = u >> 4, c4 = (u & 15) * 4;
            float4 v4 = *(const float4*)(V + (k0 + row) * 512 + h0 + c4);
            split_store(Bh, Bl, row * 72 + c4, v4);
        }
        __syncthreads();
        #pragma unroll
        for (int k16 = 0; k16 < 2; k16++) {
            uint32_t ah[4], al[4];
            ldsm_x4(ah, ahb + a_off + k16 * 32);
            ldsm_x4(al, alb + a_off + k16 * 32);
            uint32_t bh[2][4], bl[2][4];
            const uint32_t bo = (uint32_t)(((k16 * 16 + tb_row) * 72 + tb_col) * 2);
            ldsm_x4t(bh[0], bhb + bo);
            ldsm_x4t(bh[1], bhb + bo + 32);
            ldsm_x4t(bl[0], blb + bo);
            ldsm_x4t(bl[1], blb + bo + 32);
            #pragma unroll
            for (int nj = 0; nj < 4; nj++) {
                const uint32_t* ph = &bh[nj >> 1][(nj & 1) * 2];
                const uint32_t* pl = &bl[nj >> 1][(nj & 1) * 2];
                mma16816(acc[nj], ah, ph);
                mma16816(acc[nj], ah, pl);
                mma16816(acc[nj], al, ph);
            }
        }
    }
    __syncthreads();
    const int mr = wm * 16 + (lane >> 2);
    const int nc = wn * 32 + (lane & 3) * 2;
    #pragma unroll
    for (int nj = 0; nj < 4; nj++) {
        int h = nc + nj * 8;
        ts[h * 33 + mr]           = acc[nj][0];
        ts[(h + 1) * 33 + mr]     = acc[nj][1];
        ts[h * 33 + mr + 8]       = acc[nj][2];
        ts[(h + 1) * 33 + mr + 8] = acc[nj][3];
    }
    __syncthreads();
    const int h = tid >> 1, qh = (tid & 1) * 16;
    float* dst = scr + (size_t)b * 81920 + (h0 + h) * 160 + q0 + qh;
    #pragma unroll
    for (int i = 0; i < 16; i += 4) {
        float4 o = { ts[h * 33 + qh + i], ts[h * 33 + qh + i + 1],
                     ts[h * 33 + qh + i + 2], ts[h * 33 + qh + i + 3] };
        *(float4*)(dst + i) = o;
    }
}

// ------------------------------------------------------------------------------
extern "C" void kernel_launch(void* const* d_in, const int* in_sizes, int n_in,
                              void* d_out, int out_size)
{
    (void)in_sizes; (void)n_in; (void)out_size;
    const float* v    = (const float*)d_in[0];
    const float* kin  = (const float*)d_in[1];
    const float* qin  = (const float*)d_in[2];
    const float* w_v  = (const float*)d_in[3];  const float* b_v = (const float*)d_in[4];
    const float* w_k  = (const float*)d_in[5];  const float* b_k = (const float*)d_in[6];
    const float* w_q  = (const float*)d_in[7];  const float* b_q = (const float*)d_in[8];
    const float* w0   = (const float*)d_in[9];  const float* b0  = (const float*)d_in[10];
    const float* w1   = (const float*)d_in[11]; const float* b1  = (const float*)d_in[12];
    const float* wm0  = (const float*)d_in[13]; const float* bm0 = (const float*)d_in[14];
    const float* wm1  = (const float*)d_in[15]; const float* bm1 = (const float*)d_in[16];
    const float* w_bo = (const float*)d_in[17];
    const float* w_m  = (const float*)d_in[19]; const float* b_m = (const float*)d_in[20];
    float* out = (float*)d_out;

    float *vv, *w0k, *w1q, *bc, *sc, *scr;
    __nv_bfloat16 *x0, *x1, *wms, *y0, *y1;
    cudaGetSymbolAddress((void**)&vv,  g_vv);
    cudaGetSymbolAddress((void**)&w0k, g_w0k);
    cudaGetSymbolAddress((void**)&w1q, g_w1q);
    cudaGetSymbolAddress((void**)&bc,  g_bc);
    cudaGetSymbolAddress((void**)&x0,  g_x0);
    cudaGetSymbolAddress((void**)&x1,  g_x1);
    cudaGetSymbolAddress((void**)&wms, g_wms);
    cudaGetSymbolAddress((void**)&y0,  g_y0);
    cudaGetSymbolAddress((void**)&y1,  g_y1);
    cudaGetSymbolAddress((void**)&sc,  g_sc);
    cudaGetSymbolAddress((void**)&scr, g_scr);

    static int init_done = 0;
    static cudaStream_t s1;
    static cudaEvent_t evFork, evJoin;
    if (!init_done) {
        cudaFuncSetAttribute(hmma_gemm_kernel,
                             cudaFuncAttributeMaxDynamicSharedMemorySize, HM_SMEM_BYTES);
        cudaFuncSetAttribute(merge_tc_kernel,
                             cudaFuncAttributeMaxDynamicSharedMemorySize, HM_SMEM_BYTES);
        cudaFuncSetAttribute(prep_hmma_kernel,
                             cudaFuncAttributeMaxDynamicSharedMemorySize, HM_SMEM_BYTES);
        cudaStreamCreateWithFlags(&s1, cudaStreamNonBlocking);
        cudaEventCreateWithFlags(&evFork, cudaEventDisableTiming);
        cudaEventCreateWithFlags(&evJoin, cudaEventDisableTiming);
        init_done = 1;
    }

    // ---- fork: side stream runs the independent front-section work ----
    cudaEventRecord(evFork, 0);
    cudaStreamWaitEvent(s1, evFork, 0);

    // side stream: vv projection (needed only by attv) + wm split (needed by merge)
    GemmBatch gv;
    gv.A[0] = v; gv.W[0] = w_v; gv.bias[0] = b_v; gv.C[0] = vv; gv.pack[0] = 0;
    gv.A[1] = gv.A[0]; gv.W[1] = gv.W[0]; gv.bias[1] = gv.bias[0]; gv.C[1] = vv; gv.pack[1] = 0;
    gv.A[2] = gv.A[0]; gv.W[2] = gv.W[0]; gv.bias[2] = gv.bias[0]; gv.C[2] = vv; gv.pack[2] = 0;
    hmma_gemm_kernel<<<dim3(10, 8, 1), 256, HM_SMEM_BYTES, s1>>>(gv);
    wm_split_kernel<<<dim3(128, 2), 256, 0, s1>>>(wm0, wm1, wms);
    cudaEventRecord(evJoin, s1);

    // main stream: weight composition -> composed biases -> x0/x1 projections
    prep_hmma_kernel<<<dim3(4, 8, 2), 256, HM_SMEM_BYTES>>>(w0, w_k, w0k, w1, w_q, w1q);
    bias_comp_kernel<<<dim3(64, 2), 256>>>(w0, b_k, b0, w1, b_q, b1, bc);

    GemmBatch gkq;
    gkq.A[0] = kin; gkq.W[0] = w0k; gkq.bias[0] = bc;       gkq.C[0] = (float*)x0; gkq.pack[0] = 1;
    gkq.A[1] = qin; gkq.W[1] = w1q; gkq.bias[1] = bc + 512; gkq.C[1] = (float*)x1; gkq.pack[1] = 1;
    gkq.A[2] = gkq.A[0]; gkq.W[2] = gkq.W[0]; gkq.bias[2] = gkq.bias[0];
    gkq.C[2] = gkq.C[0]; gkq.pack[2] = 1;
    hmma_gemm_kernel<<<dim3(10, 8, 2), 256, HM_SMEM_BYTES>>>(gkq);

    // ---- join: merge needs wms (side) and x0/x1 (main) ----
    cudaStreamWaitEvent(0, evJoin, 0);

    MergeBatch mrg;
    mrg.X[0] = x0; mrg.WMS[0] = wms;              mrg.BM[0] = bm0; mrg.Y[0] = y0;
    mrg.X[1] = x1; mrg.WMS[1] = wms + 2*WMPLANE;  mrg.BM[1] = bm1; mrg.Y[1] = y1;
    merge_tc_kernel<<<dim3(10, 8, 16), 256, HM_SMEM_BYTES>>>(mrg);

    scores_tc<<<dim3(5, 5, 64), 128>>>(y1, y0, w_bo, sc);
    softmax_kernel<<<1280, 192>>>(sc);
    attv_tc_kernel<<<dim3(5, 8, 8), 128>>>(sc, vv, scr);

    GemmBatch g3;
    g3.A[0] = scr; g3.W[0] = w_m; g3.bias[0] = b_m; g3.C[0] = out; g3.pack[0] = 0;
    g3.A[1] = g3.A[0]; g3.W[1] = g3.W[0]; g3.bias[1] = g3.bias[0]; g3.C[1] = out; g3.pack[1] = 0;
    g3.A[2] = g3.A[0]; g3.W[2] = g3.W[0]; g3.bias[2] = g3.bias[0]; g3.C[2] = out; g3.pack[2] = 0;
    hmma_gemm_kernel<<<dim3(10, 8, 1), 256, HM_SMEM_BYTES>>>(g3);
}

// round 14
// speedup vs baseline: 1.0903x; 1.0177x over previous
#include <cuda_runtime.h>
#include <cuda_bf16.h>
#include <cstdint>

// Problem constants (fixed shapes from the reference)
#define NB_B 8
#define NB_L 160
#define NB_H 512
#define NB_C 8
#define NB_S 64
#define NB_R 8
#define NB_BL (NB_B*NB_L)   // 1280
#define SC_PLANE (NB_B*NB_L*NB_L)   // 204800
#define XPLANE (NB_BL*NB_H)         // 655360
#define WMPLANE (NB_C*NB_H*NB_S)    // 262144

// ---------------- scratch (device globals: no runtime allocation) -------------
__device__ float g_vv [NB_BL*NB_H];
__device__ float g_w0k[NB_H*NB_H];
__device__ float g_w1q[NB_H*NB_H];
__device__ float g_bc [2*NB_H];
__device__ __nv_bfloat16 g_x0 [2*XPLANE];   // hi plane | lo plane
__device__ __nv_bfloat16 g_x1 [2*XPLANE];
__device__ __nv_bfloat16 g_wms[2][2*WMPLANE]; // [tensor][hi|lo]
// Y layout: [b][c][s(64)][r(16: 8 hi | 8 lo)][l(160)] bf16
__device__ __nv_bfloat16 g_y0 [NB_B*NB_C*NB_S*16*NB_L];
__device__ __nv_bfloat16 g_y1 [NB_B*NB_C*NB_S*16*NB_L];
__device__ float g_sc [8*SC_PLANE];
__device__ float g_scr[NB_BL*NB_H];

// ======================= mma.sync helpers (sm_80+ path) =======================
__device__ __forceinline__ uint32_t smem_u32(const void* p) {
    uint32_t a;
    asm("{ .reg .u64 t; cvta.to.shared.u64 t, %1; cvt.u32.u64 %0, t; }"
        : "=r"(a) : "l"(p));
    return a;
}
__device__ __forceinline__ void mma16816(float* d, const uint32_t* a, const uint32_t* b) {
    asm volatile(
        "mma.sync.aligned.m16n8k16.row.col.f32.bf16.bf16.f32 "
        "{%0,%1,%2,%3}, {%4,%5,%6,%7}, {%8,%9}, {%0,%1,%2,%3};"
        : "+f"(d[0]), "+f"(d[1]), "+f"(d[2]), "+f"(d[3])
        : "r"(a[0]), "r"(a[1]), "r"(a[2]), "r"(a[3]), "r"(b[0]), "r"(b[1]));
}
__device__ __forceinline__ void ldsm_x4(uint32_t* r, uint32_t addr) {
    asm volatile("ldmatrix.sync.aligned.m8n8.x4.shared.b16 {%0,%1,%2,%3}, [%4];"
        : "=r"(r[0]), "=r"(r[1]), "=r"(r[2]), "=r"(r[3]) : "r"(addr));
}
__device__ __forceinline__ void ldsm_x4t(uint32_t* r, uint32_t addr) {
    asm volatile("ldmatrix.sync.aligned.m8n8.x4.trans.shared.b16 {%0,%1,%2,%3}, [%4];"
        : "=r"(r[0]), "=r"(r[1]), "=r"(r[2]), "=r"(r[3]) : "r"(addr));
}
__device__ __forceinline__ void mma1688_z(float* d, uint32_t a0, uint32_t a1, uint32_t b) {
    asm volatile(
        "mma.sync.aligned.m16n8k8.row.col.f32.bf16.bf16.f32 "
        "{%0,%1,%2,%3}, {%4,%5}, {%6}, {%7,%8,%9,%10};"
        : "=f"(d[0]), "=f"(d[1]), "=f"(d[2]), "=f"(d[3])
        : "r"(a0), "r"(a1), "r"(b), "f"(0.f), "f"(0.f), "f"(0.f), "f"(0.f));
}
__device__ __forceinline__ void mma1688_acc(float* d, uint32_t a0, uint32_t a1, uint32_t b) {
    asm volatile(
        "mma.sync.aligned.m16n8k8.row.col.f32.bf16.bf16.f32 "
        "{%0,%1,%2,%3}, {%4,%5}, {%6}, {%0,%1,%2,%3};"
        : "+f"(d[0]), "+f"(d[1]), "+f"(d[2]), "+f"(d[3])
        : "r"(a0), "r"(a1), "r"(b));
}
__device__ __forceinline__ void cp16(uint32_t dst, const void* src) {
    asm volatile("cp.async.cg.shared.global [%0], [%1], 16;" :: "r"(dst), "l"(src));
}
__device__ __forceinline__ void cp8(uint32_t dst, const void* src) {
    asm volatile("cp.async.ca.shared.global [%0], [%1], 8;" :: "r"(dst), "l"(src));
}
__device__ __forceinline__ void split_store(__nv_bfloat16* smh, __nv_bfloat16* sml,
                                            int off, float4 v) {
    __nv_bfloat162 h01 = __floats2bfloat162_rn(v.x, v.y);
    __nv_bfloat162 h23 = __floats2bfloat162_rn(v.z, v.w);
    float2 f01 = __bfloat1622float2(h01);
    float2 f23 = __bfloat1622float2(h23);
    __nv_bfloat162 l01 = __floats2bfloat162_rn(v.x - f01.x, v.y - f01.y);
    __nv_bfloat162 l23 = __floats2bfloat162_rn(v.z - f23.x, v.w - f23.y);
    *(uint2*)&smh[off] = make_uint2(*(uint32_t*)&h01, *(uint32_t*)&h23);
    *(uint2*)&sml[off] = make_uint2(*(uint32_t*)&l01, *(uint32_t*)&l23);
}
__device__ __forceinline__ uint32_t pack_hilo(float v) {
    __nv_bfloat16 hi = __float2bfloat16(v);
    __nv_bfloat16 lo = __float2bfloat16(v - __bfloat162float(hi));
    return (uint32_t)*(uint16_t*)&hi | ((uint32_t)*(uint16_t*)&lo << 16);
}
__device__ __forceinline__ void split_pair(float a, float b, uint32_t& h, uint32_t& l) {
    __nv_bfloat162 hp = __floats2bfloat162_rn(a, b);
    float2 f = __bfloat1622float2(hp);
    __nv_bfloat162 lp = __floats2bfloat162_rn(a - f.x, b - f.y);
    h = *(uint32_t*)&hp;
    l = *(uint32_t*)&lp;
}

// ================= bf16-split tensor-core GEMM: C = A @ W^T + bias ===========
// pack[z] != 0 -> store bf16 hi plane at C, lo plane at C + XPLANE.
struct GemmBatch {
    const float* A[3]; const float* W[3]; const float* bias[3]; float* C[3];
    int pack[3];
};

#define LDA_S 72
#define OFF_AH 0
#define OFF_AL (128*LDA_S)
#define OFF_WH (256*LDA_S)
#define OFF_WL (320*LDA_S)
#define HM_SMEM_BYTES (384*LDA_S*2)   // 55296

__global__ void __launch_bounds__(256) hmma_gemm_kernel(GemmBatch gb)
{
    extern __shared__ __nv_bfloat16 sm[];
    const int tid  = threadIdx.x;
    const int wid  = tid >> 5, lane = tid & 31;
    const int z = blockIdx.z;
    const float* A    = gb.A[z];
    const float* W    = gb.W[z];
    const float* bias = gb.bias[z];
    float*       C    = gb.C[z];
    const int m0 = blockIdx.x * 128;
    const int n0 = blockIdx.y * 64;
    const int wm = wid & 3, wn = wid >> 2;
    const uint32_t sb = smem_u32(sm);

    float acc[2][4][4] = {};

    const int a_row = wm * 32 + (lane & 15);
    const uint32_t a_addr0 = sb + (uint32_t)((OFF_AH + a_row * LDA_S + (lane >> 4) * 8) * 2);
    const int b_row = wn * 32 + ((lane >> 4) & 1) * 8 + (lane & 7);
    const uint32_t b_addr0 = sb + (uint32_t)((OFF_WH + b_row * LDA_S + ((lane >> 3) & 1) * 8) * 2);
    const uint32_t ALO_B = (uint32_t)((OFF_AL - OFF_AH) * 2);
    const uint32_t WLO_B = (uint32_t)((OFF_WL - OFF_WH) * 2);

    const int arow = tid >> 4, akg = (tid & 15) << 2;
    float4 pa[8], pw[4];
    #pragma unroll
    for (int it = 0; it < 8; it++)
        pa[it] = *(const float4*)(A + (m0 + arow + it * 16) * 512 + akg);
    #pragma unroll
    for (int it = 0; it < 4; it++)
        pw[it] = *(const float4*)(W + (n0 + arow + it * 16) * 512 + akg);

    for (int kc = 0; kc < 8; kc++) {
        __syncthreads();
        #pragma unroll
        for (int it = 0; it < 8; it++)
            split_store(sm + OFF_AH, sm + OFF_AL, (arow + it * 16) * LDA_S + akg, pa[it]);
        #pragma unroll
        for (int it = 0; it < 4; it++)
            split_store(sm + OFF_WH, sm + OFF_WL, (arow + it * 16) * LDA_S + akg, pw[it]);
        __syncthreads();

        if (kc < 7) {
            const int kb2 = (kc + 1) * 64;
            #pragma unroll
            for (int it = 0; it < 8; it++)
                pa[it] = *(const float4*)(A + (m0 + arow + it * 16) * 512 + kb2 + akg);
            #pragma unroll
            for (int it = 0; it < 4; it++)
                pw[it] = *(const float4*)(W + (n0 + arow + it * 16) * 512 + kb2 + akg);
        }

        #pragma unroll
        for (int k16 = 0; k16 < 4; k16++) {
            const uint32_t kb = (uint32_t)(k16 * 32);
            uint32_t ah[2][4], al[2][4];
            ldsm_x4(ah[0], a_addr0 + kb);
            ldsm_x4(ah[1], a_addr0 + (uint32_t)(16 * LDA_S * 2) + kb);
            ldsm_x4(al[0], a_addr0 + ALO_B + kb);
            ldsm_x4(al[1], a_addr0 + ALO_B + (uint32_t)(16 * LDA_S * 2) + kb);
            uint32_t bh[2][4], bl[2][4];
            ldsm_x4(bh[0], b_addr0 + kb);
            ldsm_x4(bh[1], b_addr0 + (uint32_t)(16 * LDA_S * 2) + kb);
            ldsm_x4(bl[0], b_addr0 + WLO_B + kb);
            ldsm_x4(bl[1], b_addr0 + WLO_B + (uint32_t)(16 * LDA_S * 2) + kb);
            #pragma unroll
            for (int mi = 0; mi < 2; mi++) {
                #pragma unroll
                for (int nj = 0; nj < 4; nj++) {
                    const uint32_t* bph = &bh[nj >> 1][(nj & 1) * 2];
                    const uint32_t* bpl = &bl[nj >> 1][(nj & 1) * 2];
                    mma16816(acc[mi][nj], ah[mi], bph);
                    mma16816(acc[mi][nj], ah[mi], bpl);
                    mma16816(acc[mi][nj], al[mi], bph);
                }
            }
        }
    }

    const int mrow = m0 + wm * 32 + (lane >> 2);
    const int ncol = n0 + wn * 32 + (lane & 3) * 2;
    if (gb.pack[z]) {
        __nv_bfloat16* Ch = (__nv_bfloat16*)C;
        __nv_bfloat16* Cl = Ch + XPLANE;
        #pragma unroll
        for (int mi = 0; mi < 2; mi++) {
            #pragma unroll
            for (int nj = 0; nj < 4; nj++) {
                int n = ncol + nj * 8;
                float b0 = bias[n], b1 = bias[n + 1];
                int m_a = mrow + mi * 16;
                uint32_t h, l;
                split_pair(acc[mi][nj][0] + b0, acc[mi][nj][1] + b1, h, l);
                *(uint32_t*)&Ch[m_a * 512 + n] = h;
                *(uint32_t*)&Cl[m_a * 512 + n] = l;
                split_pair(acc[mi][nj][2] + b0, acc[mi][nj][3] + b1, h, l);
                *(uint32_t*)&Ch[(m_a + 8) * 512 + n] = h;
                *(uint32_t*)&Cl[(m_a + 8) * 512 + n] = l;
            }
        }
    } else {
        #pragma unroll
        for (int mi = 0; mi < 2; mi++) {
            #pragma unroll
            for (int nj = 0; nj < 4; nj++) {
                int n = ncol + nj * 8;
                float b0 = bias[n], b1 = bias[n + 1];
                int m_a = mrow + mi * 16;
                *(float2*)&C[m_a * 512 + n]       = make_float2(acc[mi][nj][0] + b0, acc[mi][nj][1] + b1);
                *(float2*)&C[(m_a + 8) * 512 + n] = make_float2(acc[mi][nj][2] + b0, acc[mi][nj][3] + b1);
            }
        }
    }
}

// ------------------------------------------------------------------------------
// Weight composition (NN GEMM) with register prefetch (unchanged).
__global__ void __launch_bounds__(256) prep_hmma_kernel(
    const float* __restrict__ A0, const float* __restrict__ B0, float* __restrict__ C0,
    const float* __restrict__ A1, const float* __restrict__ B1, float* __restrict__ C1)
{
    extern __shared__ __nv_bfloat16 sm[];
    const int tid  = threadIdx.x;
    const int wid  = tid >> 5, lane = tid & 31;
    const float* A = blockIdx.z ? A1 : A0;
    const float* B = blockIdx.z ? B1 : B0;
    float*       C = blockIdx.z ? C1 : C0;
    const int m0 = blockIdx.x * 128;
    const int n0 = blockIdx.y * 64;
    const int wm = wid & 3, wn = wid >> 2;
    const uint32_t sb = smem_u32(sm);

    float acc[2][4][4] = {};

    const int a_row = wm * 32 + (lane & 15);
    const uint32_t a_addr0 = sb + (uint32_t)((OFF_AH + a_row * LDA_S + (lane >> 4) * 8) * 2);
    const int tb_row = ((lane >> 3) & 1) * 8 + (lane & 7);
    const int tb_col = wn * 32 + (lane >> 4) * 8;
    const uint32_t ALO_B = (uint32_t)((OFF_AL - OFF_AH) * 2);
    const uint32_t WLO_B = (uint32_t)((OFF_WL - OFF_WH) * 2);

    const int arow = tid >> 4, akg = (tid & 15) << 2;
    float4 pa[8], pw[4];
    #pragma unroll
    for (int it = 0; it < 8; it++)
        pa[it] = *(const float4*)(A + (m0 + arow + it * 16) * 512 + akg);
    #pragma unroll
    for (int it = 0; it < 4; it++)
        pw[it] = *(const float4*)(B + (arow + it * 16) * 512 + n0 + akg);

    for (int kc = 0; kc < 8; kc++) {
        __syncthreads();
        #pragma unroll
        for (int it = 0; it < 8; it++)
            split_store(sm + OFF_AH, sm + OFF_AL, (arow + it * 16) * LDA_S + akg, pa[it]);
        #pragma unroll
        for (int it = 0; it < 4; it++)
            split_store(sm + OFF_WH, sm + OFF_WL, (arow + it * 16) * LDA_S + akg, pw[it]);
        __syncthreads();

        if (kc < 7) {
            const int kb2 = (kc + 1) * 64;
            #pragma unroll
            for (int it = 0; it < 8; it++)
                pa[it] = *(const float4*)(A + (m0 + arow + it * 16) * 512 + kb2 + akg);
            #pragma unroll
            for (int it = 0; it < 4; it++)
                pw[it] = *(const float4*)(B + (kb2 + arow + it * 16) * 512 + n0 + akg);
        }

        #pragma unroll
        for (int k16 = 0; k16 < 4; k16++) {
            const uint32_t kb = (uint32_t)(k16 * 32);
            uint32_t ah[2][4], al[2][4];
            ldsm_x4(ah[0], a_addr0 + kb);
            ldsm_x4(ah[1], a_addr0 + (uint32_t)(16 * LDA_S * 2) + kb);
            ldsm_x4(al[0], a_addr0 + ALO_B + kb);
            ldsm_x4(al[1], a_addr0 + ALO_B + (uint32_t)(16 * LDA_S * 2) + kb);
            uint32_t bh[2][4], bl[2][4];
            const uint32_t bo = sb + (uint32_t)((OFF_WH + (k16 * 16 + tb_row) * LDA_S + tb_col) * 2);
            ldsm_x4t(bh[0], bo);
            ldsm_x4t(bh[1], bo + 32);
            ldsm_x4t(bl[0], bo + WLO_B);
            ldsm_x4t(bl[1], bo + WLO_B + 32);
            #pragma unroll
            for (int mi = 0; mi < 2; mi++) {
                #pragma unroll
                for (int nj = 0; nj < 4; nj++) {
                    const uint32_t* bph = &bh[nj >> 1][(nj & 1) * 2];
                    const uint32_t* bpl = &bl[nj >> 1][(nj & 1) * 2];
                    mma16816(acc[mi][nj], ah[mi], bph);
                    mma16816(acc[mi][nj], ah[mi], bpl);
                    mma16816(acc[mi][nj], al[mi], bph);
                }
            }
        }
    }

    const int mrow = m0 + wm * 32 + (lane >> 2);
    const int ncol = n0 + wn * 32 + (lane & 3) * 2;
    #pragma unroll
    for (int mi = 0; mi < 2; mi++) {
        #pragma unroll
        for (int nj = 0; nj < 4; nj++) {
            int n = ncol + nj * 8;
            int m_a = mrow + mi * 16;
            *(float2*)&C[m_a * 512 + n]       = make_float2(acc[mi][nj][0], acc[mi][nj][1]);
            *(float2*)&C[(m_a + 8) * 512 + n] = make_float2(acc[mi][nj][2], acc[mi][nj][3]);
        }
    }
}

// ------------------------------------------------------------------------------
// Composed biases, float4-vectorized: bc[z][n] = dot(wz[n,:], b_in_z) + b_out_z[n].
__global__ void __launch_bounds__(256) bias_comp_kernel(
    const float* __restrict__ w0, const float* __restrict__ bk, const float* __restrict__ b0,
    const float* __restrict__ w1, const float* __restrict__ bq, const float* __restrict__ b1,
    float* __restrict__ bc)
{
    const int z = blockIdx.y;
    const float* W  = z ? w1 : w0;
    const float* bi = z ? bq : bk;
    const float* bo = z ? b1 : b0;
    const int warp = threadIdx.x >> 5, lane = threadIdx.x & 31;
    const int n = blockIdx.x * 8 + warp;
    const float* row = W + n * 512;
    float s = 0.f;
    #pragma unroll
    for (int h4 = 0; h4 < 4; h4++) {
        int h = (lane + h4 * 32) * 4;
        float4 wv = *(const float4*)(row + h);
        float4 bv = *(const float4*)(bi + h);
        s = fmaf(wv.x, bv.x, s);
        s = fmaf(wv.y, bv.y, s);
        s = fmaf(wv.z, bv.z, s);
        s = fmaf(wv.w, bv.w, s);
    }
    #pragma unroll
    for (int o = 16; o; o >>= 1) s += __shfl_xor_sync(0xffffffffu, s, o);
    if (lane == 0) bc[z * 512 + n] = s + bo[n];
}

// ------------------------------------------------------------------------------
// wm split: fp32 merge weights -> bf16 hi/lo planes, 16B stores.
__global__ void __launch_bounds__(256) wm_split_kernel(
    const float* __restrict__ wm0, const float* __restrict__ wm1,
    __nv_bfloat16* __restrict__ wms)
{
    const int t = blockIdx.y;
    const float* src = t ? wm1 : wm0;
    __nv_bfloat16* dh = wms + (size_t)t * 2 * WMPLANE;
    __nv_bfloat16* dl = dh + WMPLANE;
    const int i8 = (blockIdx.x * 256 + threadIdx.x) * 8;
    float4 v0 = *(const float4*)(src + i8);
    float4 v1 = *(const float4*)(src + i8 + 4);
    uint32_t h[4], l[4];
    split_pair(v0.x, v0.y, h[0], l[0]);
    split_pair(v0.z, v0.w, h[1], l[1]);
    split_pair(v1.x, v1.y, h[2], l[2]);
    split_pair(v1.z, v1.w, h[3], l[3]);
    *(uint4*)&dh[i8] = make_uint4(h[0], h[1], h[2], h[3]);
    *(uint4*)&dl[i8] = make_uint4(l[0], l[1], l[2], l[3]);
}

// ------------------------------------------------------------------------------
// Tensor-core merge (cp.async pre-split planes, stride 72).
struct MergeBatch {
    const __nv_bfloat16* X[2];
    const __nv_bfloat16* WMS[2];
    const float* BM[2];
    __nv_bfloat16* Y[2];
};

__global__ void __launch_bounds__(256) merge_tc_kernel(MergeBatch mb)
{
    extern __shared__ __nv_bfloat16 sm[];
    const int tid  = threadIdx.x;
    const int wid  = tid >> 5, lane = tid & 31;
    const int zz = blockIdx.z;
    const int tensor = zz >> 3, c = zz & 7;
    const __nv_bfloat16* X   = mb.X[tensor];
    const __nv_bfloat16* WMS = mb.WMS[tensor];
    const float* BM = mb.BM[tensor];
    __nv_bfloat16* Y = mb.Y[tensor];
    const int m0 = blockIdx.x * 128;
    const int r  = blockIdx.y;
    const int n0 = r * 64;
    const int wm = wid & 3, wn = wid >> 2;
    const uint32_t sb = smem_u32(sm);

    #pragma unroll
    for (int it = 0; it < 16; it++) {
        int u = tid + it * 256;
        int plane = u >> 11, v = u & 2047;
        int row = v >> 4, g = v & 15;
        const __nv_bfloat16* src = X + plane * XPLANE
            + (size_t)(m0 + row) * 512 + c * 64 + g * 4;
        uint32_t dst = sb + (uint32_t)(((plane ? OFF_AL : OFF_AH) + row * LDA_S + g * 4) * 2);
        cp8(dst, src);
    }
    #pragma unroll
    for (int it = 0; it < 8; it++) {
        int u = tid + it * 256;
        int plane = u >> 10, v = u & 1023;
        int row = v >> 4, g = v & 15;
        const __nv_bfloat16* src = WMS + plane * WMPLANE
            + (size_t)(c * 512 + n0 + row) * 64 + g * 4;
        uint32_t dst = sb + (uint32_t)(((plane ? OFF_WL : OFF_WH) + row * LDA_S + g * 4) * 2);
        cp8(dst, src);
    }
    asm volatile("cp.async.commit_group;" ::: "memory");
    asm volatile("cp.async.wait_group 0;" ::: "memory");
    __syncthreads();

    const int a_row = wm * 32 + (lane & 15);
    const uint32_t a_addr0 = sb + (uint32_t)((OFF_AH + a_row * LDA_S + (lane >> 4) * 8) * 2);
    const int b_row = wn * 32 + ((lane >> 4) & 1) * 8 + (lane & 7);
    const uint32_t b_addr0 = sb + (uint32_t)((OFF_WH + b_row * LDA_S + ((lane >> 3) & 1) * 8) * 2);
    const uint32_t ALO_B = (uint32_t)((OFF_AL - OFF_AH) * 2);
    const uint32_t WLO_B = (uint32_t)((OFF_WL - OFF_WH) * 2);

    float acc[2][4][4] = {};
    #pragma unroll
    for (int k16 = 0; k16 < 4; k16++) {
        const uint32_t kb = (uint32_t)(k16 * 32);
        uint32_t ah[2][4], al[2][4];
        ldsm_x4(ah[0], a_addr0 + kb);
        ldsm_x4(ah[1], a_addr0 + (uint32_t)(16 * LDA_S * 2) + kb);
        ldsm_x4(al[0], a_addr0 + ALO_B + kb);
        ldsm_x4(al[1], a_addr0 + ALO_B + (uint32_t)(16 * LDA_S * 2) + kb);
        uint32_t bh[2][4], bl[2][4];
        ldsm_x4(bh[0], b_addr0 + kb);
        ldsm_x4(bh[1], b_addr0 + (uint32_t)(16 * LDA_S * 2) + kb);
        ldsm_x4(bl[0], b_addr0 + WLO_B + kb);
        ldsm_x4(bl[1], b_addr0 + WLO_B + (uint32_t)(16 * LDA_S * 2) + kb);
        #pragma unroll
        for (int mi = 0; mi < 2; mi++) {
            #pragma unroll
            for (int nj = 0; nj < 4; nj++) {
                const uint32_t* bph = &bh[nj >> 1][(nj & 1) * 2];
                const uint32_t* bpl = &bl[nj >> 1][(nj & 1) * 2];
                mma16816(acc[mi][nj], ah[mi], bph);
                mma16816(acc[mi][nj], ah[mi], bpl);
                mma16816(acc[mi][nj], al[mi], bph);
            }
        }
    }

    __syncthreads();
    uint32_t* ps = (uint32_t*)sm;
    const int mbase = wm * 32 + (lane >> 2);
    const int tbase = wn * 32 + (lane & 3) * 2;
    #pragma unroll
    for (int mi = 0; mi < 2; mi++) {
        #pragma unroll
        for (int nj = 0; nj < 4; nj++) {
            int tt = tbase + nj * 8;
            float bb0 = BM[c * 512 + n0 + tt];
            float bb1 = BM[c * 512 + n0 + tt + 1];
            #pragma unroll
            for (int e = 0; e < 4; e++) {
                int mm = mbase + mi * 16 + ((e >> 1) ? 8 : 0);
                int tc2 = tt + (e & 1);
                ps[tc2 * 132 + mm] = pack_hilo(acc[mi][nj][e] + ((e & 1) ? bb1 : bb0));
            }
        }
    }
    __syncthreads();

    #pragma unroll
    for (int it = 0; it < 8; it++) {
        int u = tid + it * 256;
        int st = u >> 5, g = u & 31;
        int ml = g * 4;
        uint32_t p0 = ps[st * 132 + ml + 0];
        uint32_t p1 = ps[st * 132 + ml + 1];
        uint32_t p2 = ps[st * 132 + ml + 2];
        uint32_t p3 = ps[st * 132 + ml + 3];
        uint32_t hi01 = (p0 & 0xffffu) | (p1 << 16);
        uint32_t hi23 = (p2 & 0xffffu) | (p3 << 16);
        uint32_t lo01 = (p0 >> 16) | (p1 & 0xffff0000u);
        uint32_t lo23 = (p2 >> 16) | (p3 & 0xffff0000u);
        int m = m0 + ml;
        int b = m / 160, l = m % 160;
        size_t base = ((size_t)((b * 8 + c) * 64 + st) * 16 + r) * 160 + l;
        *(uint2*)&Y[base]            = make_uint2(hi01, hi23);
        *(uint2*)&Y[base + 8 * 160]  = make_uint2(lo01, lo23);
    }
}

// ------------------------------------------------------------------------------
// Tensor-core scores (unchanged).
__global__ void __launch_bounds__(128) scores_tc(
    const __nv_bfloat16* __restrict__ Y1, const __nv_bfloat16* __restrict__ Y0,
    const float* __restrict__ wbo, float* __restrict__ SC)
{
    __shared__ __nv_bfloat16 SB[2][2][128*40];
    __shared__ float swb[64];
    const int tid = threadIdx.x;
    const int warp = tid >> 5, lane = tid & 31;
    const int qt = blockIdx.x, kt = blockIdx.y;
    const int b = blockIdx.z >> 3, c = blockIdx.z & 7;
    const int qoff = (warp >> 1) * 16, koff = (warp & 1) * 16;
    if (tid < 64) swb[tid] = wbo[c * 64 + tid];

    const uint32_t sbb = smem_u32(SB);
    const int t4 = lane >> 3, rr = lane & 7;
    const int lrow = ((t4 & 2) ? 8 : 0) + rr;
    const uint32_t aoff = (uint32_t)((lrow * 40 + qoff + (t4 & 1) * 8) * 2);
    const uint32_t boff = (uint32_t)((lrow * 40 + koff + (t4 & 1) * 8) * 2);

    const int su   = tid;
    const int cbase = (b * 8 + c) * 1024;

    auto issue = [&](int oct, int buf) {
        const int sbase = cbase + oct * 128;
        #pragma unroll
        for (int it = 0; it < 8; it++) {
            int u = su + it * 128;
            int half = u >> 9, v = u & 511;
            int row = v >> 2, ch = v & 3;
            const __nv_bfloat16* src = (half ? Y0 : Y1)
                + (size_t)(sbase + row) * 160 + (half ? kt : qt) * 32 + ch * 8;
            uint32_t dst = sbb + (uint32_t)(((buf * 2 + half) * 5120 + row * 40 + ch * 8) * 2);
            cp16(dst, src);
        }
        asm volatile("cp.async.commit_group;" ::: "memory");
    };

    issue(0, 0);

    float num[2][4] = {}, den[2][4] = {};
    for (int oct = 0; oct < 8; oct++) {
        const int buf = oct & 1;
        if (oct < 7) {
            issue(oct + 1, buf ^ 1);
            asm volatile("cp.async.wait_group 1;" ::: "memory");
        } else {
            asm volatile("cp.async.wait_group 0;" ::: "memory");
        }
        __syncthreads();
        const uint32_t s1b = sbb + (uint32_t)(buf * 2 * 10240);
        const uint32_t s0b = s1b + 10240;
        #pragma unroll
        for (int st = 0; st < 8; st++) {
            const uint32_t tb = (uint32_t)(st * 1280);
            uint32_t a[4], bv[4];
            ldsm_x4t(a,  s1b + tb + aoff);
            ldsm_x4t(bv, s0b + tb + boff);
            float z0[4], z1[4];
            mma1688_z  (z0, a[0], a[1], bv[0]);
            mma1688_acc(z0, a[0], a[1], bv[2]);
            mma1688_acc(z0, a[2], a[3], bv[0]);
            mma1688_z  (z1, a[0], a[1], bv[1]);
            mma1688_acc(z1, a[0], a[1], bv[3]);
            mma1688_acc(z1, a[2], a[3], bv[1]);
            const float wb = swb[oct * 8 + st];
            #pragma unroll
            for (int e = 0; e < 4; e++) {
                {
                    float az = fabsf(z0[e]);
                    den[0][e] += az;
                    float s;
                    asm("sqrt.approx.f32 %0, %1;" : "=f"(s) : "f"(az));
                    uint32_t sb2 = (__float_as_uint(s) & 0x7fffffffu)
                                 | (__float_as_uint(z0[e]) & 0x80000000u);
                    num[0][e] = fmaf(wb, __uint_as_float(sb2), num[0][e]);
                }
                {
                    float az = fabsf(z1[e]);
                    den[1][e] += az;
                    float s;
                    asm("sqrt.approx.f32 %0, %1;" : "=f"(s) : "f"(az));
                    uint32_t sb2 = (__float_as_uint(s) & 0x7fffffffu)
                                 | (__float_as_uint(z1[e]) & 0x80000000u);
                    num[1][e] = fmaf(wb, __uint_as_float(sb2), num[1][e]);
                }
            }
        }
        __syncthreads();
    }

    const int q = qt*32 + qoff + (lane >> 2);
    const int k = kt*32 + koff + (lane & 3)*2;
    float* p0 = SC + (size_t)c * SC_PLANE + (size_t)(b*160 + q)*160 + k;
    *(float2*)(p0)             = make_float2(num[0][0] * rsqrtf(fmaxf(den[0][0], 1e-24f)),
                                             num[0][1] * rsqrtf(fmaxf(den[0][1], 1e-24f)));
    *(float2*)(p0 + 8)         = make_float2(num[1][0] * rsqrtf(fmaxf(den[1][0], 1e-24f)),
                                             num[1][1] * rsqrtf(fmaxf(den[1][1], 1e-24f)));
    *(float2*)(p0 + 8*160)     = make_float2(num[0][2] * rsqrtf(fmaxf(den[0][2], 1e-24f)),
                                             num[0][3] * rsqrtf(fmaxf(den[0][3], 1e-24f)));
    *(float2*)(p0 + 8*160 + 8) = make_float2(num[1][2] * rsqrtf(fmaxf(den[1][2], 1e-24f)),
                                             num[1][3] * rsqrtf(fmaxf(den[1][3], 1e-24f)));
}

// ------------------------------------------------------------------------------
__global__ void __launch_bounds__(192) softmax_kernel(float* __restrict__ sc)
{
    const int row = blockIdx.x;
    float* p = sc + (size_t)row*160;
    const int t = threadIdx.x;
    __shared__ float red[6], red2[6];
    float x = -3.0e38f;
    if (t < 160) {
        x = 0.f;
        #pragma unroll
        for (int i = 0; i < 8; i++) x += p[(size_t)i*SC_PLANE + t];
    }
    float v = x;
    #pragma unroll
    for (int o = 16; o; o >>= 1) v = fmaxf(v, __shfl_xor_sync(0xffffffffu, v, o));
    if ((t & 31) == 0) red[t >> 5] = v;
    __syncthreads();
    float m = red[0];
    #pragma unroll
    for (int i = 1; i < 6; i++) m = fmaxf(m, red[i]);
    float e = (t < 160) ? expf(x - m) : 0.f;
    float sv = e;
    #pragma unroll
    for (int o = 16; o; o >>= 1) sv += __shfl_xor_sync(0xffffffffu, sv, o);
    if ((t & 31) == 0) red2[t >> 5] = sv;
    __syncthreads();
    float ssum = 0.f;
    #pragma unroll
    for (int i = 0; i < 6; i++) ssum += red2[i];
    if (t < 160) p[t] = e / ssum;
}

// ------------------------------------------------------------------------------
// Tensor-core attv (NN GEMM) fused with transpose-scramble (unchanged).
__global__ void __launch_bounds__(128) attv_tc_kernel(
    const float* __restrict__ att, const float* __restrict__ vv,
    float* __restrict__ scr)
{
    __shared__ __nv_bfloat16 Ah[32*40], Al[32*40], Bh[32*72], Bl[32*72];
    __shared__ float ts[64*33];
    const int tid = threadIdx.x;
    const int warp = tid >> 5, lane = tid & 31;
    const int q0 = blockIdx.x * 32, h0 = blockIdx.y * 64, b = blockIdx.z;
    const int wm = warp & 1, wn = warp >> 1;
    const float* A = att + (size_t)b * 25600;
    const float* V = vv + (size_t)b * 81920;
    const uint32_t ahb = smem_u32(Ah), alb = smem_u32(Al);
    const uint32_t bhb = smem_u32(Bh), blb = smem_u32(Bl);
    const uint32_t a_off = (uint32_t)(((wm * 16 + (lane & 15)) * 40 + (lane >> 4) * 8) * 2);
    const int tb_row = ((lane >> 3) & 1) * 8 + (lane & 7);
    const int tb_col = wn * 32 + (lane >> 4) * 8;

    float acc[4][4] = {};
    for (int kc = 0; kc < 5; kc++) {
        const int k0 = kc * 32;
        __syncthreads();
        #pragma unroll
        for (int it = 0; it < 2; it++) {
            int u = tid + it * 128;
            int row = u >> 3, c4 = (u & 7) * 4;
            float4 v4 = *(const float4*)(A + (q0 + row) * 160 + k0 + c4);
            split_store(Ah, Al, row * 40 + c4, v4);
        }
        #pragma unroll
        for (int it = 0; it < 4; it++) {
            int u = tid + it * 128;
            int row = u >> 4, c4 = (u & 15) * 4;
            float4 v4 = *(const float4*)(V + (k0 + row) * 512 + h0 + c4);
            split_store(Bh, Bl, row * 72 + c4, v4);
        }
        __syncthreads();
        #pragma unroll
        for (int k16 = 0; k16 < 2; k16++) {
            uint32_t ah[4], al[4];
            ldsm_x4(ah, ahb + a_off + k16 * 32);
            ldsm_x4(al, alb + a_off + k16 * 32);
            uint32_t bh[2][4], bl[2][4];
            const uint32_t bo = (uint32_t)(((k16 * 16 + tb_row) * 72 + tb_col) * 2);
            ldsm_x4t(bh[0], bhb + bo);
            ldsm_x4t(bh[1], bhb + bo + 32);
            ldsm_x4t(bl[0], blb + bo);
            ldsm_x4t(bl[1], blb + bo + 32);
            #pragma unroll
            for (int nj = 0; nj < 4; nj++) {
                const uint32_t* ph = &bh[nj >> 1][(nj & 1) * 2];
                const uint32_t* pl = &bl[nj >> 1][(nj & 1) * 2];
                mma16816(acc[nj], ah, ph);
                mma16816(acc[nj], ah, pl);
                mma16816(acc[nj], al, ph);
            }
        }
    }
    __syncthreads();
    const int mr = wm * 16 + (lane >> 2);
    const int nc = wn * 32 + (lane & 3) * 2;
    #pragma unroll
    for (int nj = 0; nj < 4; nj++) {
        int h = nc + nj * 8;
        ts[h * 33 + mr]           = acc[nj][0];
        ts[(h + 1) * 33 + mr]     = acc[nj][1];
        ts[h * 33 + mr + 8]       = acc[nj][2];
        ts[(h + 1) * 33 + mr + 8] = acc[nj][3];
    }
    __syncthreads();
    const int h = tid >> 1, qh = (tid & 1) * 16;
    float* dst = scr + (size_t)b * 81920 + (h0 + h) * 160 + q0 + qh;
    #pragma unroll
    for (int i = 0; i < 16; i += 4) {
        float4 o = { ts[h * 33 + qh + i], ts[h * 33 + qh + i + 1],
                     ts[h * 33 + qh + i + 2], ts[h * 33 + qh + i + 3] };
        *(float4*)(dst + i) = o;
    }
}

// ------------------------------------------------------------------------------
extern "C" void kernel_launch(void* const* d_in, const int* in_sizes, int n_in,
                              void* d_out, int out_size)
{
    (void)in_sizes; (void)n_in; (void)out_size;
    const float* v    = (const float*)d_in[0];
    const float* kin  = (const float*)d_in[1];
    const float* qin  = (const float*)d_in[2];
    const float* w_v  = (const float*)d_in[3];  const float* b_v = (const float*)d_in[4];
    const float* w_k  = (const float*)d_in[5];  const float* b_k = (const float*)d_in[6];
    const float* w_q  = (const float*)d_in[7];  const float* b_q = (const float*)d_in[8];
    const float* w0   = (const float*)d_in[9];  const float* b0  = (const float*)d_in[10];
    const float* w1   = (const float*)d_in[11]; const float* b1  = (const float*)d_in[12];
    const float* wm0  = (const float*)d_in[13]; const float* bm0 = (const float*)d_in[14];
    const float* wm1  = (const float*)d_in[15]; const float* bm1 = (const float*)d_in[16];
    const float* w_bo = (const float*)d_in[17];
    const float* w_m  = (const float*)d_in[19]; const float* b_m = (const float*)d_in[20];
    float* out = (float*)d_out;

    float *vv, *w0k, *w1q, *bc, *sc, *scr;
    __nv_bfloat16 *x0, *x1, *wms, *y0, *y1;
    cudaGetSymbolAddress((void**)&vv,  g_vv);
    cudaGetSymbolAddress((void**)&w0k, g_w0k);
    cudaGetSymbolAddress((void**)&w1q, g_w1q);
    cudaGetSymbolAddress((void**)&bc,  g_bc);
    cudaGetSymbolAddress((void**)&x0,  g_x0);
    cudaGetSymbolAddress((void**)&x1,  g_x1);
    cudaGetSymbolAddress((void**)&wms, g_wms);
    cudaGetSymbolAddress((void**)&y0,  g_y0);
    cudaGetSymbolAddress((void**)&y1,  g_y1);
    cudaGetSymbolAddress((void**)&sc,  g_sc);
    cudaGetSymbolAddress((void**)&scr, g_scr);

    static int init_done = 0;
    static cudaStream_t s1;
    static cudaEvent_t evFork, evBias, evJoin;
    if (!init_done) {
        cudaFuncSetAttribute(hmma_gemm_kernel,
                             cudaFuncAttributeMaxDynamicSharedMemorySize, HM_SMEM_BYTES);
        cudaFuncSetAttribute(merge_tc_kernel,
                             cudaFuncAttributeMaxDynamicSharedMemorySize, HM_SMEM_BYTES);
        cudaFuncSetAttribute(prep_hmma_kernel,
                             cudaFuncAttributeMaxDynamicSharedMemorySize, HM_SMEM_BYTES);
        cudaStreamCreateWithFlags(&s1, cudaStreamNonBlocking);
        cudaEventCreateWithFlags(&evFork, cudaEventDisableTiming);
        cudaEventCreateWithFlags(&evBias, cudaEventDisableTiming);
        cudaEventCreateWithFlags(&evJoin, cudaEventDisableTiming);
        init_done = 1;
    }

    // ---- fork: side stream runs input-only work off the critical path ----
    cudaEventRecord(evFork, 0);
    cudaStreamWaitEvent(s1, evFork, 0);

    // side stream: composed biases FIRST (needed by gemm_kq), then vv + wm split
    bias_comp_kernel<<<dim3(64, 2), 256, 0, s1>>>(w0, b_k, b0, w1, b_q, b1, bc);
    cudaEventRecord(evBias, s1);
    GemmBatch gv;
    gv.A[0] = v; gv.W[0] = w_v; gv.bias[0] = b_v; gv.C[0] = vv; gv.pack[0] = 0;
    gv.A[1] = gv.A[0]; gv.W[1] = gv.W[0]; gv.bias[1] = gv.bias[0]; gv.C[1] = vv; gv.pack[1] = 0;
    gv.A[2] = gv.A[0]; gv.W[2] = gv.W[0]; gv.bias[2] = gv.bias[0]; gv.C[2] = vv; gv.pack[2] = 0;
    hmma_gemm_kernel<<<dim3(10, 8, 1), 256, HM_SMEM_BYTES, s1>>>(gv);
    wm_split_kernel<<<dim3(128, 2), 256, 0, s1>>>(wm0, wm1, wms);
    cudaEventRecord(evJoin, s1);

    // main stream: weight composition -> x0/x1 projections
    prep_hmma_kernel<<<dim3(4, 8, 2), 256, HM_SMEM_BYTES>>>(w0, w_k, w0k, w1, w_q, w1q);
    cudaStreamWaitEvent(0, evBias, 0);

    GemmBatch gkq;
    gkq.A[0] = kin; gkq.W[0] = w0k; gkq.bias[0] = bc;       gkq.C[0] = (float*)x0; gkq.pack[0] = 1;
    gkq.A[1] = qin; gkq.W[1] = w1q; gkq.bias[1] = bc + 512; gkq.C[1] = (float*)x1; gkq.pack[1] = 1;
    gkq.A[2] = gkq.A[0]; gkq.W[2] = gkq.W[0]; gkq.bias[2] = gkq.bias[0];
    gkq.C[2] = gkq.C[0]; gkq.pack[2] = 1;
    hmma_gemm_kernel<<<dim3(10, 8, 2), 256, HM_SMEM_BYTES>>>(gkq);

    // ---- join: merge needs wms (side) and x0/x1 (main) ----
    cudaStreamWaitEvent(0, evJoin, 0);

    MergeBatch mrg;
    mrg.X[0] = x0; mrg.WMS[0] = wms;              mrg.BM[0] = bm0; mrg.Y[0] = y0;
    mrg.X[1] = x1; mrg.WMS[1] = wms + 2*WMPLANE;  mrg.BM[1] = bm1; mrg.Y[1] = y1;
    merge_tc_kernel<<<dim3(10, 8, 16), 256, HM_SMEM_BYTES>>>(mrg);

    scores_tc<<<dim3(5, 5, 64), 128>>>(y1, y0, w_bo, sc);
    softmax_kernel<<<1280, 192>>>(sc);
    attv_tc_kernel<<<dim3(5, 8, 8), 128>>>(sc, vv, scr);

    GemmBatch g3;
    g3.A[0] = scr; g3.W[0] = w_m; g3.bias[0] = b_m; g3.C[0] = out; g3.pack[0] = 0;
    g3.A[1] = g3.A[0]; g3.W[1] = g3.W[0]; g3.bias[1] = g3.bias[0]; g3.C[1] = out; g3.pack[1] = 0;
    g3.A[2] = g3.A[0]; g3.W[2] = g3.W[0]; g3.bias[2] = g3.bias[0]; g3.C[2] = out; g3.pack[2] = 0;
    hmma_gemm_kernel<<<dim3(10, 8, 1), 256, HM_SMEM_BYTES>>>(g3);
}